// round 6
// baseline (speedup 1.0000x reference)
#include <cuda_runtime.h>
#include <math.h>

// Scratch (device globals -- no runtime allocation allowed)
__device__ float g_X0[2048 * 1024];   // enc layer0 input gates  [s*32+b][j]
__device__ float g_Xd[3200 * 1024];   // dec input gates         [t*32+b][j]
__device__ float g_enc[32 * 64 * 256];// enc_out [b][s][h]
__device__ float g_htop[32 * 256];    // final top-layer h
__device__ float g_H2[3200 * 256];    // decoder hiddens [b*100+t][h]

__device__ __forceinline__ float sigf(float x) { return 1.f / (1.f + expf(-x)); }

__device__ __forceinline__ float wred(float v) {
#pragma unroll
    for (int o = 16; o; o >>= 1) v += __shfl_xor_sync(0xffffffffu, v, o);
    return v;
}

// packed f32x2 FMA (sm_100+ PTX; FFMA2 = 2x scalar FFMA throughput)
__device__ __forceinline__ unsigned long long pk2(float lo, float hi) {
    unsigned long long r;
    asm("mov.b64 %0, {%1,%2};" : "=l"(r) : "f"(lo), "f"(hi));
    return r;
}
__device__ __forceinline__ void fma2(unsigned long long& d, unsigned long long a,
                                     unsigned long long b) {
    asm("fma.rn.f32x2 %0, %1, %2, %0;" : "+l"(d) : "l"(a), "l"(b));
}
__device__ __forceinline__ void upk2(unsigned long long v, float& lo, float& hi) {
    asm("mov.b64 {%0,%1}, %2;" : "=f"(lo), "=f"(hi) : "l"(v));
}

// ============================================================================
// k_pre: X0[r][j] = b0[j] + emb(q)[r] . Wih0[j]   (r = s*32+b, 2048 rows)
//        Xd[r][j] = db[j] + emb(d)[r] . dWih[j][0:128]  (r = t*32+b, 3200 rows)
// blocks 0..511 -> X0 (128 row-tiles x 4 j-tiles); 512..1311 -> Xd (200 x 4)
// ============================================================================
__global__ void k_pre(const int* __restrict__ qids, const int* __restrict__ sids,
                      const float* __restrict__ encE, const float* __restrict__ Wih0,
                      const float* __restrict__ b0, const float* __restrict__ decE,
                      const float* __restrict__ dWih, const float* __restrict__ db)
{
    __shared__ float4 a_s[16 * 32];
    const int blk = blockIdx.x, tid = threadIdx.x;
    const bool isX0 = blk < 512;
    const int u = isX0 ? blk : blk - 512;
    const int rt = u >> 2, jb = (u & 3) << 8;
    const float4* Ef = (const float4*)(isX0 ? encE : decE);
#pragma unroll
    for (int i = 0; i < 2; ++i) {
        int lin = tid + i * 256;
        int rr = lin >> 5, e4 = lin & 31;
        int row = rt * 16 + rr, b = row & 31, idx = row >> 5;
        int tok = isX0 ? qids[b * 64 + idx] : (idx == 0 ? 1 : sids[b * 100 + idx - 1]);
        a_s[rr * 32 + e4] = Ef[(size_t)tok * 32 + e4];
    }
    __syncthreads();
    const int j = jb + tid;
    const float4* Wf = (const float4*)(isX0 ? (Wih0 + j * 128) : (dWih + j * 384));
    float acc[16];
#pragma unroll
    for (int r = 0; r < 16; ++r) acc[r] = 0.f;
#pragma unroll 4
    for (int e4 = 0; e4 < 32; ++e4) {
        float4 w = __ldg(Wf + e4);
#pragma unroll
        for (int r = 0; r < 16; ++r) {
            float4 a = a_s[r * 32 + e4];
            acc[r] += a.x * w.x + a.y * w.y + a.z * w.z + a.w * w.w;
        }
    }
    const float bias = isX0 ? __ldg(b0 + j) : __ldg(db + j);
    float* dst = isX0 ? g_X0 : g_Xd;
#pragma unroll
    for (int r = 0; r < 16; ++r) dst[(rt * 16 + r) * 1024 + j] = bias + acc[r];
}

// ============================================================================
// k_enc: one CTA per batch element b; 64 steps of fused 2-layer LSTM.
// Gate GEMV: warp-per-row, coalesced LDG.128 weight reads + shfl reduction.
// ============================================================================
__global__ void k_enc(const float* __restrict__ Whh0, const float* __restrict__ Wih1,
                      const float* __restrict__ Whh1, const float* __restrict__ b1)
{
    __shared__ float h0[256], c0[256], h1[256], c1[256], gt[1024];
    const int b = blockIdx.x, tid = threadIdx.x;
    const int w = tid >> 5, l = tid & 31;
    h0[tid] = 0.f; c0[tid] = 0.f; h1[tid] = 0.f; c1[tid] = 0.f;
    __syncthreads();

    for (int s = 0; s < 64; ++s) {
        // ---- layer0 gates: gt[j] = X0[s,b][j] + h0 . Whh0[j] ----
        float4 hA = ((const float4*)h0)[l], hB = ((const float4*)h0)[l + 32];
        const float* x0 = g_X0 + (s * 32 + b) * 1024;
        for (int j = w; j < 1024; j += 8) {
            const float4* W = (const float4*)(Whh0 + j * 256);
            float4 wa = __ldg(W + l), wb = __ldg(W + l + 32);
            float p = wa.x * hA.x + wa.y * hA.y + wa.z * hA.z + wa.w * hA.w
                    + wb.x * hB.x + wb.y * hB.y + wb.z * hB.z + wb.w * hB.w;
            p = wred(p);
            if (l == 0) gt[j] = p + __ldg(x0 + j);
        }
        __syncthreads();
        // ---- cell0 ----
        {
            float gi = sigf(gt[tid]), gf = sigf(gt[tid + 256]);
            float gg = tanhf(gt[tid + 512]), go = sigf(gt[tid + 768]);
            float cc = gf * c0[tid] + gi * gg;
            c0[tid] = cc;
            h0[tid] = go * tanhf(cc);
        }
        __syncthreads();
        // ---- layer1 gates: gt[j] = b1[j] + h0 . Wih1[j] + h1 . Whh1[j] ----
        float4 xA = ((const float4*)h0)[l], xB = ((const float4*)h0)[l + 32];
        float4 gA = ((const float4*)h1)[l], gB = ((const float4*)h1)[l + 32];
        for (int j = w; j < 1024; j += 8) {
            const float4* Wi = (const float4*)(Wih1 + j * 256);
            const float4* Wh = (const float4*)(Whh1 + j * 256);
            float4 wa = __ldg(Wi + l), wb = __ldg(Wi + l + 32);
            float4 va = __ldg(Wh + l), vb = __ldg(Wh + l + 32);
            float p = wa.x * xA.x + wa.y * xA.y + wa.z * xA.z + wa.w * xA.w
                    + wb.x * xB.x + wb.y * xB.y + wb.z * xB.z + wb.w * xB.w
                    + va.x * gA.x + va.y * gA.y + va.z * gA.z + va.w * gA.w
                    + vb.x * gB.x + vb.y * gB.y + vb.z * gB.z + vb.w * gB.w;
            p = wred(p);
            if (l == 0) gt[j] = p + __ldg(b1 + j);
        }
        __syncthreads();
        // ---- cell1 ----
        {
            float gi = sigf(gt[tid]), gf = sigf(gt[tid + 256]);
            float gg = tanhf(gt[tid + 512]), go = sigf(gt[tid + 768]);
            float cc = gf * c1[tid] + gi * gg;
            c1[tid] = cc;
            float hh = go * tanhf(cc);
            h1[tid] = hh;
            g_enc[(b * 64 + s) * 256 + tid] = hh;
        }
        __syncthreads();
    }
    g_htop[b * 256 + tid] = h1[tid];
}

// ============================================================================
// k_dec: one CTA per b; 100 steps of attention + LSTM cell (c_in == 0).
// ============================================================================
__global__ void k_dec(const float* __restrict__ dWih, const float* __restrict__ dWhh)
{
    __shared__ float h[256], ctx[256], sc[64], gt[1024], red[2];
    const int b = blockIdx.x, tid = threadIdx.x;
    const int w = tid >> 5, l = tid & 31;
    h[tid] = g_htop[b * 256 + tid];
    __syncthreads();
    const float* enc = g_enc + b * 64 * 256;

    for (int t = 0; t < 100; ++t) {
        // ---- scores[s] = h . enc[s]  (4 threads per s) ----
        {
            int s = tid >> 2, q = tid & 3;
            const float4* er = (const float4*)(enc + s * 256) + q * 16;
            const float4* hf = (const float4*)h + q * 16;
            float p = 0.f;
#pragma unroll
            for (int i = 0; i < 16; ++i) {
                float4 e4 = __ldg(er + i); float4 h4 = hf[i];
                p += e4.x * h4.x + e4.y * h4.y + e4.z * h4.z + e4.w * h4.w;
            }
            p += __shfl_xor_sync(0xffffffffu, p, 1);
            p += __shfl_xor_sync(0xffffffffu, p, 2);
            if (q == 0) sc[s] = p;
        }
        __syncthreads();
        // ---- softmax max ----
        if (tid < 32) {
            float m = fmaxf(sc[tid], sc[tid + 32]);
#pragma unroll
            for (int o = 16; o; o >>= 1) m = fmaxf(m, __shfl_xor_sync(0xffffffffu, m, o));
            if (tid == 0) red[0] = m;
        }
        __syncthreads();
        if (tid < 64) sc[tid] = expf(sc[tid] - red[0]);
        __syncthreads();
        if (tid < 32) {
            float ssum = wred(sc[tid] + sc[tid + 32]);
            if (tid == 0) red[1] = 1.f / ssum;
        }
        __syncthreads();
        // ---- ctx[k] = (1/Z) * sum_s e[s] * enc[s][k]  (coalesced over k) ----
        {
            float a = 0.f;
            const float* ec = enc + tid;
#pragma unroll 4
            for (int s = 0; s < 64; ++s) a += sc[s] * __ldg(ec + s * 256);
            ctx[tid] = a * red[1];
        }
        __syncthreads();
        // ---- gates: gt[j] = Xd[t,b][j] + ctx . dWih[j][128:384] + h . dWhh[j] ----
        float4 cA = ((const float4*)ctx)[l], cB = ((const float4*)ctx)[l + 32];
        float4 hA = ((const float4*)h)[l],   hB = ((const float4*)h)[l + 32];
        const float* xd = g_Xd + (t * 32 + b) * 1024;
        for (int j = w; j < 1024; j += 8) {
            const float4* Wc = (const float4*)(dWih + j * 384 + 128);
            const float4* Wh = (const float4*)(dWhh + j * 256);
            float4 wa = __ldg(Wc + l), wb = __ldg(Wc + l + 32);
            float4 va = __ldg(Wh + l), vb = __ldg(Wh + l + 32);
            float p = wa.x * cA.x + wa.y * cA.y + wa.z * cA.z + wa.w * cA.w
                    + wb.x * cB.x + wb.y * cB.y + wb.z * cB.z + wb.w * cB.w
                    + va.x * hA.x + va.y * hA.y + va.z * hA.z + va.w * hA.w
                    + vb.x * hB.x + vb.y * hB.y + vb.z * hB.z + vb.w * hB.w;
            p = wred(p);
            if (l == 0) gt[j] = p + __ldg(xd + j);
        }
        __syncthreads();
        // ---- cell (c_in = 0): c2 = sig(i)*tanh(g); h2 = sig(o)*tanh(c2) ----
        {
            float gi = sigf(gt[tid]), gg = tanhf(gt[tid + 512]), go = sigf(gt[tid + 768]);
            float h2 = go * tanhf(gi * gg);
            h[tid] = h2;
            g_H2[(b * 100 + t) * 256 + tid] = h2;
        }
        __syncthreads();
    }
}

// ============================================================================
// k_out: out[r][v] = H2[r] . Wout[v] + bout[v], r = b*100+t. 128x128x16 tiles,
// 256 threads, 8x8 microtile, fma.rn.f32x2 accumulators, reg-prefetch pipeline.
// M=3200=25*128, N=32000=250*128, K=256=16*16: no tails.
// ============================================================================
__global__ void __launch_bounds__(256) k_out(const float* __restrict__ Wout,
                                             const float* __restrict__ bout,
                                             float* __restrict__ out)
{
    __shared__ float As[16][132], Bs[16][132];
    const int tid = threadIdx.x;
    const int rb = blockIdx.y * 128, vb = blockIdx.x * 128;
    const int tx = tid & 15, ty = tid >> 4;
    const int r0 = tid >> 2, k0 = (tid & 3) * 4;          // load slot 0
    const int r1 = (tid + 256) >> 2, k1 = ((tid + 256) & 3) * 4;  // load slot 1

    unsigned long long acc[8][4];
#pragma unroll
    for (int i = 0; i < 8; ++i)
#pragma unroll
        for (int j = 0; j < 4; ++j) acc[i][j] = 0ull;

    const float* A = g_H2;
    float4 a0 = *(const float4*)(A + (rb + r0) * 256 + k0);
    float4 a1 = *(const float4*)(A + (rb + r1) * 256 + k1);
    float4 bv0 = *(const float4*)(Wout + (size_t)(vb + r0) * 256 + k0);
    float4 bv1 = *(const float4*)(Wout + (size_t)(vb + r1) * 256 + k1);

    for (int kc = 0; kc < 16; ++kc) {
        As[k0 + 0][r0] = a0.x; As[k0 + 1][r0] = a0.y; As[k0 + 2][r0] = a0.z; As[k0 + 3][r0] = a0.w;
        As[k1 + 0][r1] = a1.x; As[k1 + 1][r1] = a1.y; As[k1 + 2][r1] = a1.z; As[k1 + 3][r1] = a1.w;
        Bs[k0 + 0][r0] = bv0.x; Bs[k0 + 1][r0] = bv0.y; Bs[k0 + 2][r0] = bv0.z; Bs[k0 + 3][r0] = bv0.w;
        Bs[k1 + 0][r1] = bv1.x; Bs[k1 + 1][r1] = bv1.y; Bs[k1 + 2][r1] = bv1.z; Bs[k1 + 3][r1] = bv1.w;
        __syncthreads();
        if (kc < 15) {
            int kb = (kc + 1) * 16;
            a0 = *(const float4*)(A + (rb + r0) * 256 + kb + k0);
            a1 = *(const float4*)(A + (rb + r1) * 256 + kb + k1);
            bv0 = *(const float4*)(Wout + (size_t)(vb + r0) * 256 + kb + k0);
            bv1 = *(const float4*)(Wout + (size_t)(vb + r1) * 256 + kb + k1);
        }
#pragma unroll
        for (int k = 0; k < 16; ++k) {
            float4 aA = *(const float4*)&As[k][ty * 4];
            float4 aB = *(const float4*)&As[k][ty * 4 + 64];
            float4 bA = *(const float4*)&Bs[k][tx * 4];
            float4 bB = *(const float4*)&Bs[k][tx * 4 + 64];
            unsigned long long bp[4] = { pk2(bA.x, bA.y), pk2(bA.z, bA.w),
                                         pk2(bB.x, bB.y), pk2(bB.z, bB.w) };
            float av[8] = { aA.x, aA.y, aA.z, aA.w, aB.x, aB.y, aB.z, aB.w };
#pragma unroll
            for (int i = 0; i < 8; ++i) {
                unsigned long long ap = pk2(av[i], av[i]);
#pragma unroll
                for (int j = 0; j < 4; ++j) fma2(acc[i][j], ap, bp[j]);
            }
        }
        __syncthreads();
    }

    // epilogue
    float bo[8];
#pragma unroll
    for (int j = 0; j < 4; ++j) {
        int cb = ((j >> 1) ? 64 : 0) + tx * 4 + (j & 1) * 2;
        bo[j * 2]     = __ldg(bout + vb + cb);
        bo[j * 2 + 1] = __ldg(bout + vb + cb + 1);
    }
#pragma unroll
    for (int i = 0; i < 8; ++i) {
        int row = rb + ((i < 4) ? (ty * 4 + i) : (64 + ty * 4 + i - 4));
        float* orow = out + (size_t)row * 32000 + vb;
#pragma unroll
        for (int j = 0; j < 4; ++j) {
            int cb = ((j >> 1) ? 64 : 0) + tx * 4 + (j & 1) * 2;
            float lo, hi; upk2(acc[i][j], lo, hi);
            *(float2*)(orow + cb) = make_float2(lo + bo[j * 2], hi + bo[j * 2 + 1]);
        }
    }
}

extern "C" void kernel_launch(void* const* d_in, const int* in_sizes, int n_in,
                              void* d_out, int out_size)
{
    (void)in_sizes; (void)n_in; (void)out_size;
    const int*   qids = (const int*)d_in[0];
    const int*   sids = (const int*)d_in[1];
    const float* encE = (const float*)d_in[2];
    const float* Wih0 = (const float*)d_in[3];
    const float* Whh0 = (const float*)d_in[4];
    const float* b0   = (const float*)d_in[5];
    const float* Wih1 = (const float*)d_in[6];
    const float* Whh1 = (const float*)d_in[7];
    const float* b1   = (const float*)d_in[8];
    const float* decE = (const float*)d_in[9];
    const float* dWih = (const float*)d_in[10];
    const float* dWhh = (const float*)d_in[11];
    const float* db   = (const float*)d_in[12];
    const float* Wout = (const float*)d_in[13];
    const float* bout = (const float*)d_in[14];
    float* out = (float*)d_out;

    k_pre<<<1312, 256>>>(qids, sids, encE, Wih0, b0, decE, dWih, db);
    k_enc<<<32, 256>>>(Whh0, Wih1, Whh1, b1);
    k_dec<<<32, 256>>>(dWih, dWhh);
    k_out<<<dim3(250, 25), 256>>>(Wout, bout, out);
}

// round 7
// speedup vs baseline: 1.4245x; 1.4245x over previous
#include <cuda_runtime.h>
#include <math.h>

// Scratch (device globals -- no runtime allocation allowed)
__device__ float g_X0[2048 * 1024];   // enc layer0 input gates  [s*32+b][j]
__device__ float g_Xd[3200 * 1024];   // dec input gates         [t*32+b][j]
__device__ float g_enc[32 * 64 * 256];// enc_out [b][s][h]
__device__ float g_htop[32 * 256];    // final top-layer h
__device__ float g_H2[3200 * 256];    // decoder hiddens [b*100+t][h]
// transposed weights [k][j] for broadcast-FMA GEMVs
__device__ float g_WT0[256 * 1024];   // Whh0^T
__device__ float g_WT1[512 * 1024];   // [Wih1 ; Whh1]^T  (rows 0-255: Wih1, 256-511: Whh1)
__device__ float g_WTd[512 * 1024];   // [dWih[:,128:384] ; dWhh]^T

__device__ __forceinline__ float sigf(float x) { return 1.f / (1.f + expf(-x)); }

__device__ __forceinline__ float wred(float v) {
#pragma unroll
    for (int o = 16; o; o >>= 1) v += __shfl_xor_sync(0xffffffffu, v, o);
    return v;
}

// packed f32x2 FMA (sm_100+ PTX; FFMA2 = 2x scalar FFMA throughput)
__device__ __forceinline__ unsigned long long pk2(float lo, float hi) {
    unsigned long long r;
    asm("mov.b64 %0, {%1,%2};" : "=l"(r) : "f"(lo), "f"(hi));
    return r;
}
__device__ __forceinline__ void fma2(unsigned long long& d, unsigned long long a,
                                     unsigned long long b) {
    asm("fma.rn.f32x2 %0, %1, %2, %0;" : "+l"(d) : "l"(a), "l"(b));
}
__device__ __forceinline__ void upk2(unsigned long long v, float& lo, float& hi) {
    asm("mov.b64 {%0,%1}, %2;" : "=f"(lo), "=f"(hi) : "l"(v));
}

// ============================================================================
// k_tr: transpose recurrent weight matrices into [k][j] layout.
// One CTA per output row k (1280 rows of 1024); thread handles 4 j.
// ============================================================================
__global__ void k_tr(const float* __restrict__ Whh0, const float* __restrict__ Wih1,
                     const float* __restrict__ Whh1, const float* __restrict__ dWih,
                     const float* __restrict__ dWhh)
{
    const int row = blockIdx.x;          // 0..1279
    const int j0 = threadIdx.x * 4;
    const float* src;
    long stride;
    float* dst;
    int k;
    if (row < 256) {                      // WT0 <- Whh0
        k = row; src = Whh0 + k; stride = 256; dst = g_WT0 + k * 1024;
    } else if (row < 768) {               // WT1 <- Wih1 / Whh1
        k = row - 256;
        if (k < 256) { src = Wih1 + k; } else { src = Whh1 + (k - 256); }
        stride = 256; dst = g_WT1 + k * 1024;
    } else {                              // WTd <- dWih ctx part / dWhh
        k = row - 768;
        if (k < 256) { src = dWih + 128 + k; stride = 384; }
        else         { src = dWhh + (k - 256); stride = 256; }
        dst = g_WTd + k * 1024;
    }
    float4 v;
    v.x = __ldg(src + (long)(j0 + 0) * stride);
    v.y = __ldg(src + (long)(j0 + 1) * stride);
    v.z = __ldg(src + (long)(j0 + 2) * stride);
    v.w = __ldg(src + (long)(j0 + 3) * stride);
    *(float4*)(dst + j0) = v;
}

// ============================================================================
// k_pre: X0[r][j] = b0[j] + emb(q)[r] . Wih0[j]   (r = s*32+b, 2048 rows)
//        Xd[r][j] = db[j] + emb(d)[r] . dWih[j][0:128]  (r = t*32+b, 3200 rows)
// ============================================================================
__global__ void k_pre(const int* __restrict__ qids, const int* __restrict__ sids,
                      const float* __restrict__ encE, const float* __restrict__ Wih0,
                      const float* __restrict__ b0, const float* __restrict__ decE,
                      const float* __restrict__ dWih, const float* __restrict__ db)
{
    __shared__ __align__(16) float4 a_s[16 * 32];
    const int blk = blockIdx.x, tid = threadIdx.x;
    const bool isX0 = blk < 512;
    const int u = isX0 ? blk : blk - 512;
    const int rt = u >> 2, jb = (u & 3) << 8;
    const float4* Ef = (const float4*)(isX0 ? encE : decE);
#pragma unroll
    for (int i = 0; i < 2; ++i) {
        int lin = tid + i * 256;
        int rr = lin >> 5, e4 = lin & 31;
        int row = rt * 16 + rr, b = row & 31, idx = row >> 5;
        int tok = isX0 ? qids[b * 64 + idx] : (idx == 0 ? 1 : sids[b * 100 + idx - 1]);
        a_s[rr * 32 + e4] = Ef[(size_t)tok * 32 + e4];
    }
    __syncthreads();
    const int j = jb + tid;
    const float4* Wf = (const float4*)(isX0 ? (Wih0 + j * 128) : (dWih + j * 384));
    float acc[16];
#pragma unroll
    for (int r = 0; r < 16; ++r) acc[r] = 0.f;
#pragma unroll 4
    for (int e4 = 0; e4 < 32; ++e4) {
        float4 w = __ldg(Wf + e4);
#pragma unroll
        for (int r = 0; r < 16; ++r) {
            float4 a = a_s[r * 32 + e4];
            acc[r] += a.x * w.x + a.y * w.y + a.z * w.z + a.w * w.w;
        }
    }
    const float bias = isX0 ? __ldg(b0 + j) : __ldg(db + j);
    float* dst = isX0 ? g_X0 : g_Xd;
#pragma unroll
    for (int r = 0; r < 16; ++r) dst[(rt * 16 + r) * 1024 + j] = bias + acc[r];
}

// ============================================================================
// k_enc: one CTA per batch element; 64 steps of fused 2-layer LSTM.
// Broadcast-FMA GEMV: thread tid owns gate columns [4tid,4tid+4); k-loop
// reads smem h (broadcast) and coalesced transposed-weight rows. No shuffles.
// ============================================================================
__global__ void __launch_bounds__(256) k_enc(const float* __restrict__ b1)
{
    __shared__ __align__(16) float hh[512];   // [0..255]=h0, [256..511]=h1
    __shared__ __align__(16) float gt[1024];
    const int b = blockIdx.x, tid = threadIdx.x;
    float c0 = 0.f, c1 = 0.f;
    hh[tid] = 0.f; hh[256 + tid] = 0.f;
    const float4 b1v = *(const float4*)(b1 + 4 * tid);
    const float4* W0 = (const float4*)g_WT0 + tid;   // row k at offset k*256
    const float4* W1 = (const float4*)g_WT1 + tid;
    const float4* h4 = (const float4*)hh;
    __syncthreads();

    for (int s = 0; s < 64; ++s) {
        // ---- layer0 gates: acc_j = X0 + sum_k h0[k] * WT0[k][j] ----
        float4 acc = *(const float4*)(g_X0 + (s * 32 + b) * 1024 + 4 * tid);
#pragma unroll 4
        for (int k4 = 0; k4 < 64; ++k4) {
            float4 hv = h4[k4];
            float4 w0 = __ldg(W0 + (k4 * 4 + 0) * 256);
            float4 w1 = __ldg(W0 + (k4 * 4 + 1) * 256);
            float4 w2 = __ldg(W0 + (k4 * 4 + 2) * 256);
            float4 w3 = __ldg(W0 + (k4 * 4 + 3) * 256);
            acc.x += hv.x * w0.x + hv.y * w1.x + hv.z * w2.x + hv.w * w3.x;
            acc.y += hv.x * w0.y + hv.y * w1.y + hv.z * w2.y + hv.w * w3.y;
            acc.z += hv.x * w0.z + hv.y * w1.z + hv.z * w2.z + hv.w * w3.z;
            acc.w += hv.x * w0.w + hv.y * w1.w + hv.z * w2.w + hv.w * w3.w;
        }
        *(float4*)(gt + 4 * tid) = acc;
        __syncthreads();
        {   // cell0 update (c0 in register; column tid)
            float gi = sigf(gt[tid]), gf = sigf(gt[tid + 256]);
            float gg = tanhf(gt[tid + 512]), go = sigf(gt[tid + 768]);
            c0 = gf * c0 + gi * gg;
            hh[tid] = go * tanhf(c0);
        }
        __syncthreads();
        // ---- layer1 gates: vec = [h0 ; h1], WT1 ----
        float4 acc1 = b1v;
#pragma unroll 4
        for (int k4 = 0; k4 < 128; ++k4) {
            float4 hv = h4[k4];
            float4 w0 = __ldg(W1 + (k4 * 4 + 0) * 256);
            float4 w1 = __ldg(W1 + (k4 * 4 + 1) * 256);
            float4 w2 = __ldg(W1 + (k4 * 4 + 2) * 256);
            float4 w3 = __ldg(W1 + (k4 * 4 + 3) * 256);
            acc1.x += hv.x * w0.x + hv.y * w1.x + hv.z * w2.x + hv.w * w3.x;
            acc1.y += hv.x * w0.y + hv.y * w1.y + hv.z * w2.y + hv.w * w3.y;
            acc1.z += hv.x * w0.z + hv.y * w1.z + hv.z * w2.z + hv.w * w3.z;
            acc1.w += hv.x * w0.w + hv.y * w1.w + hv.z * w2.w + hv.w * w3.w;
        }
        *(float4*)(gt + 4 * tid) = acc1;
        __syncthreads();
        {   // cell1 update
            float gi = sigf(gt[tid]), gf = sigf(gt[tid + 256]);
            float gg = tanhf(gt[tid + 512]), go = sigf(gt[tid + 768]);
            c1 = gf * c1 + gi * gg;
            float h1v = go * tanhf(c1);
            hh[256 + tid] = h1v;
            g_enc[(b * 64 + s) * 256 + tid] = h1v;
        }
        __syncthreads();
    }
    g_htop[b * 256 + tid] = hh[256 + tid];
}

// ============================================================================
// k_dec: one CTA per b; 100 steps of attention + LSTM cell (c_in == 0).
// Same broadcast-FMA gate GEMV with vec = [ctx ; h] and WTd.
// ============================================================================
__global__ void __launch_bounds__(256) k_dec()
{
    __shared__ __align__(16) float hh[512];   // [0..255]=ctx, [256..511]=h
    __shared__ __align__(16) float gt[1024];
    __shared__ float sc[64], red[1];
    const int b = blockIdx.x, tid = threadIdx.x;
    hh[256 + tid] = g_htop[b * 256 + tid];
    const float* enc = g_enc + b * 64 * 256;
    const float4* Wd = (const float4*)g_WTd + tid;
    const float4* h4 = (const float4*)hh;
    __syncthreads();

    for (int t = 0; t < 100; ++t) {
        // ---- scores[s] = h . enc[s]  (4 threads per s) ----
        {
            int s = tid >> 2, q = tid & 3;
            const float4* er = (const float4*)(enc + s * 256) + q * 16;
            const float4* hf = (const float4*)(hh + 256) + q * 16;
            float p = 0.f;
#pragma unroll
            for (int i = 0; i < 16; ++i) {
                float4 e4 = __ldg(er + i); float4 hv = hf[i];
                p += e4.x * hv.x + e4.y * hv.y + e4.z * hv.z + e4.w * hv.w;
            }
            p += __shfl_xor_sync(0xffffffffu, p, 1);
            p += __shfl_xor_sync(0xffffffffu, p, 2);
            if (q == 0) sc[s] = p;
        }
        __syncthreads();
        // ---- softmax (warp 0 only) ----
        if (tid < 32) {
            float s0 = sc[tid], s1 = sc[tid + 32];
            float m = fmaxf(s0, s1);
#pragma unroll
            for (int o = 16; o; o >>= 1) m = fmaxf(m, __shfl_xor_sync(0xffffffffu, m, o));
            float e0 = expf(s0 - m), e1 = expf(s1 - m);
            sc[tid] = e0; sc[tid + 32] = e1;
            float ssum = wred(e0 + e1);
            if (tid == 0) red[0] = 1.f / ssum;
        }
        __syncthreads();
        // ---- ctx[k] = (1/Z) * sum_s e[s] * enc[s][k] ----
        {
            float a = 0.f;
            const float* ec = enc + tid;
#pragma unroll 8
            for (int s = 0; s < 64; ++s) a += sc[s] * __ldg(ec + s * 256);
            hh[tid] = a * red[0];
        }
        __syncthreads();
        // ---- gates: acc_j = Xd + sum_k [ctx;h][k] * WTd[k][j] ----
        float4 acc = *(const float4*)(g_Xd + (t * 32 + b) * 1024 + 4 * tid);
#pragma unroll 4
        for (int k4 = 0; k4 < 128; ++k4) {
            float4 hv = h4[k4];
            float4 w0 = __ldg(Wd + (k4 * 4 + 0) * 256);
            float4 w1 = __ldg(Wd + (k4 * 4 + 1) * 256);
            float4 w2 = __ldg(Wd + (k4 * 4 + 2) * 256);
            float4 w3 = __ldg(Wd + (k4 * 4 + 3) * 256);
            acc.x += hv.x * w0.x + hv.y * w1.x + hv.z * w2.x + hv.w * w3.x;
            acc.y += hv.x * w0.y + hv.y * w1.y + hv.z * w2.y + hv.w * w3.y;
            acc.z += hv.x * w0.z + hv.y * w1.z + hv.z * w2.z + hv.w * w3.z;
            acc.w += hv.x * w0.w + hv.y * w1.w + hv.z * w2.w + hv.w * w3.w;
        }
        *(float4*)(gt + 4 * tid) = acc;
        __syncthreads();
        // ---- cell (c_in = 0): h2 = sig(o)*tanh(sig(i)*tanh(g)) ----
        {
            float gi = sigf(gt[tid]), gg = tanhf(gt[tid + 512]), go = sigf(gt[tid + 768]);
            float h2 = go * tanhf(gi * gg);
            hh[256 + tid] = h2;
            g_H2[(b * 100 + t) * 256 + tid] = h2;
        }
        __syncthreads();
    }
}

// ============================================================================
// k_out: out[r][v] = H2[r] . Wout[v] + bout[v].  128x128x16 tiles, 256 thr,
// 8x8 microtile, fma.rn.f32x2 accumulators, register-prefetch pipeline.
// (unchanged from the passing round: ~83% of FFMA2 ceiling)
// ============================================================================
__global__ void __launch_bounds__(256) k_out(const float* __restrict__ Wout,
                                             const float* __restrict__ bout,
                                             float* __restrict__ out)
{
    __shared__ __align__(16) float As[16][132], Bs[16][132];
    const int tid = threadIdx.x;
    const int rb = blockIdx.y * 128, vb = blockIdx.x * 128;
    const int tx = tid & 15, ty = tid >> 4;
    const int r0 = tid >> 2, k0 = (tid & 3) * 4;
    const int r1 = (tid + 256) >> 2, k1 = ((tid + 256) & 3) * 4;

    unsigned long long acc[8][4];
#pragma unroll
    for (int i = 0; i < 8; ++i)
#pragma unroll
        for (int j = 0; j < 4; ++j) acc[i][j] = 0ull;

    const float* A = g_H2;
    float4 a0 = *(const float4*)(A + (rb + r0) * 256 + k0);
    float4 a1 = *(const float4*)(A + (rb + r1) * 256 + k1);
    float4 bv0 = *(const float4*)(Wout + (size_t)(vb + r0) * 256 + k0);
    float4 bv1 = *(const float4*)(Wout + (size_t)(vb + r1) * 256 + k1);

    for (int kc = 0; kc < 16; ++kc) {
        As[k0 + 0][r0] = a0.x; As[k0 + 1][r0] = a0.y; As[k0 + 2][r0] = a0.z; As[k0 + 3][r0] = a0.w;
        As[k1 + 0][r1] = a1.x; As[k1 + 1][r1] = a1.y; As[k1 + 2][r1] = a1.z; As[k1 + 3][r1] = a1.w;
        Bs[k0 + 0][r0] = bv0.x; Bs[k0 + 1][r0] = bv0.y; Bs[k0 + 2][r0] = bv0.z; Bs[k0 + 3][r0] = bv0.w;
        Bs[k1 + 0][r1] = bv1.x; Bs[k1 + 1][r1] = bv1.y; Bs[k1 + 2][r1] = bv1.z; Bs[k1 + 3][r1] = bv1.w;
        __syncthreads();
        if (kc < 15) {
            int kb = (kc + 1) * 16;
            a0 = *(const float4*)(A + (rb + r0) * 256 + kb + k0);
            a1 = *(const float4*)(A + (rb + r1) * 256 + kb + k1);
            bv0 = *(const float4*)(Wout + (size_t)(vb + r0) * 256 + kb + k0);
            bv1 = *(const float4*)(Wout + (size_t)(vb + r1) * 256 + kb + k1);
        }
#pragma unroll
        for (int k = 0; k < 16; ++k) {
            float4 aA = *(const float4*)&As[k][ty * 4];
            float4 aB = *(const float4*)&As[k][ty * 4 + 64];
            float4 bA = *(const float4*)&Bs[k][tx * 4];
            float4 bB = *(const float4*)&Bs[k][tx * 4 + 64];
            unsigned long long bp[4] = { pk2(bA.x, bA.y), pk2(bA.z, bA.w),
                                         pk2(bB.x, bB.y), pk2(bB.z, bB.w) };
            float av[8] = { aA.x, aA.y, aA.z, aA.w, aB.x, aB.y, aB.z, aB.w };
#pragma unroll
            for (int i = 0; i < 8; ++i) {
                unsigned long long ap = pk2(av[i], av[i]);
#pragma unroll
                for (int j = 0; j < 4; ++j) fma2(acc[i][j], ap, bp[j]);
            }
        }
        __syncthreads();
    }

    float bo[8];
#pragma unroll
    for (int j = 0; j < 4; ++j) {
        int cb = ((j >> 1) ? 64 : 0) + tx * 4 + (j & 1) * 2;
        bo[j * 2]     = __ldg(bout + vb + cb);
        bo[j * 2 + 1] = __ldg(bout + vb + cb + 1);
    }
#pragma unroll
    for (int i = 0; i < 8; ++i) {
        int row = rb + ((i < 4) ? (ty * 4 + i) : (64 + ty * 4 + i - 4));
        float* orow = out + (size_t)row * 32000 + vb;
#pragma unroll
        for (int j = 0; j < 4; ++j) {
            int cb = ((j >> 1) ? 64 : 0) + tx * 4 + (j & 1) * 2;
            float lo, hi; upk2(acc[i][j], lo, hi);
            *(float2*)(orow + cb) = make_float2(lo + bo[j * 2], hi + bo[j * 2 + 1]);
        }
    }
}

extern "C" void kernel_launch(void* const* d_in, const int* in_sizes, int n_in,
                              void* d_out, int out_size)
{
    (void)in_sizes; (void)n_in; (void)out_size;
    const int*   qids = (const int*)d_in[0];
    const int*   sids = (const int*)d_in[1];
    const float* encE = (const float*)d_in[2];
    const float* Wih0 = (const float*)d_in[3];
    const float* Whh0 = (const float*)d_in[4];
    const float* b0   = (const float*)d_in[5];
    const float* Wih1 = (const float*)d_in[6];
    const float* Whh1 = (const float*)d_in[7];
    const float* b1   = (const float*)d_in[8];
    const float* decE = (const float*)d_in[9];
    const float* dWih = (const float*)d_in[10];
    const float* dWhh = (const float*)d_in[11];
    const float* db   = (const float*)d_in[12];
    const float* Wout = (const float*)d_in[13];
    const float* bout = (const float*)d_in[14];
    float* out = (float*)d_out;

    k_tr<<<1280, 256>>>(Whh0, Wih1, Whh1, dWih, dWhh);
    k_pre<<<1312, 256>>>(qids, sids, encE, Wih0, b0, decE, dWih, db);
    k_enc<<<32, 256>>>(b1);
    k_dec<<<32, 256>>>();
    k_out<<<dim3(250, 25), 256>>>(Wout, bout, out);
}

// round 8
// speedup vs baseline: 2.9433x; 2.0662x over previous
#include <cuda_runtime.h>
#include <math.h>

// Scratch (device globals -- no runtime allocation allowed)
__device__ float g_X0[2048 * 1024];   // enc layer0 input gates  [s*32+b][j]
__device__ float g_Xd[3200 * 1024];   // dec input gates         [t*32+b][j]
__device__ float g_enc[32 * 64 * 256];// enc_out [b][s][h]
__device__ float g_htop[32 * 256];    // final top-layer h
__device__ float g_H2[3200 * 256];    // decoder hiddens [b*100+t][h]
// transposed weights [k][j] for broadcast-FMA GEMVs
__device__ float g_WT0[256 * 1024];   // Whh0^T
__device__ float g_WT1[512 * 1024];   // [Wih1 ; Whh1]^T
__device__ float g_WTd[512 * 1024];   // [dWih[:,128:384] ; dWhh]^T

__device__ __forceinline__ float sigf(float x) { return 1.f / (1.f + expf(-x)); }

__device__ __forceinline__ float wred(float v) {
#pragma unroll
    for (int o = 16; o; o >>= 1) v += __shfl_xor_sync(0xffffffffu, v, o);
    return v;
}

// DSMEM store: write v to the same smem offset in cluster CTA `rank`
__device__ __forceinline__ void stc(float* p, int rank, float v) {
    unsigned a = (unsigned)__cvta_generic_to_shared(p);
    unsigned r;
    asm volatile("mapa.shared::cluster.u32 %0, %1, %2;" : "=r"(r) : "r"(a), "r"(rank));
    asm volatile("st.shared::cluster.f32 [%0], %1;" :: "r"(r), "f"(v) : "memory");
}
__device__ __forceinline__ void csync() {
    asm volatile("barrier.cluster.arrive.aligned;" ::: "memory");
    asm volatile("barrier.cluster.wait.aligned;" ::: "memory");
}

// packed f32x2 FMA (sm_100+ PTX)
__device__ __forceinline__ unsigned long long pk2(float lo, float hi) {
    unsigned long long r;
    asm("mov.b64 %0, {%1,%2};" : "=l"(r) : "f"(lo), "f"(hi));
    return r;
}
__device__ __forceinline__ void fma2(unsigned long long& d, unsigned long long a,
                                     unsigned long long b) {
    asm("fma.rn.f32x2 %0, %1, %2, %0;" : "+l"(d) : "l"(a), "l"(b));
}
__device__ __forceinline__ void upk2(unsigned long long v, float& lo, float& hi) {
    asm("mov.b64 {%0,%1}, %2;" : "=f"(lo), "=f"(hi) : "l"(v));
}

// ============================================================================
// k_tr: transpose recurrent weights into [k][j] layout (1280 rows of 1024)
// ============================================================================
__global__ void k_tr(const float* __restrict__ Whh0, const float* __restrict__ Wih1,
                     const float* __restrict__ Whh1, const float* __restrict__ dWih,
                     const float* __restrict__ dWhh)
{
    const int row = blockIdx.x;
    const int j0 = threadIdx.x * 4;
    const float* src; long stride; float* dst; int k;
    if (row < 256) {
        k = row; src = Whh0 + k; stride = 256; dst = g_WT0 + k * 1024;
    } else if (row < 768) {
        k = row - 256;
        src = (k < 256) ? (Wih1 + k) : (Whh1 + (k - 256));
        stride = 256; dst = g_WT1 + k * 1024;
    } else {
        k = row - 768;
        if (k < 256) { src = dWih + 128 + k; stride = 384; }
        else         { src = dWhh + (k - 256); stride = 256; }
        dst = g_WTd + k * 1024;
    }
    float4 v;
    v.x = __ldg(src + (long)(j0 + 0) * stride);
    v.y = __ldg(src + (long)(j0 + 1) * stride);
    v.z = __ldg(src + (long)(j0 + 2) * stride);
    v.w = __ldg(src + (long)(j0 + 3) * stride);
    *(float4*)(dst + j0) = v;
}

// ============================================================================
// k_pre: X0[r][j] = b0[j] + emb(q)[r].Wih0[j]; Xd[r][j] = db[j] + emb(d)[r].dWih[j][0:128]
// ============================================================================
__global__ void k_pre(const int* __restrict__ qids, const int* __restrict__ sids,
                      const float* __restrict__ encE, const float* __restrict__ Wih0,
                      const float* __restrict__ b0, const float* __restrict__ decE,
                      const float* __restrict__ dWih, const float* __restrict__ db)
{
    __shared__ __align__(16) float4 a_s[16 * 32];
    const int blk = blockIdx.x, tid = threadIdx.x;
    const bool isX0 = blk < 512;
    const int u = isX0 ? blk : blk - 512;
    const int rt = u >> 2, jb = (u & 3) << 8;
    const float4* Ef = (const float4*)(isX0 ? encE : decE);
#pragma unroll
    for (int i = 0; i < 2; ++i) {
        int lin = tid + i * 256;
        int rr = lin >> 5, e4 = lin & 31;
        int row = rt * 16 + rr, b = row & 31, idx = row >> 5;
        int tok = isX0 ? qids[b * 64 + idx] : (idx == 0 ? 1 : sids[b * 100 + idx - 1]);
        a_s[rr * 32 + e4] = Ef[(size_t)tok * 32 + e4];
    }
    __syncthreads();
    const int j = jb + tid;
    const float4* Wf = (const float4*)(isX0 ? (Wih0 + j * 128) : (dWih + j * 384));
    float acc[16];
#pragma unroll
    for (int r = 0; r < 16; ++r) acc[r] = 0.f;
#pragma unroll 4
    for (int e4 = 0; e4 < 32; ++e4) {
        float4 w = __ldg(Wf + e4);
#pragma unroll
        for (int r = 0; r < 16; ++r) {
            float4 a = a_s[r * 32 + e4];
            acc[r] += a.x * w.x + a.y * w.y + a.z * w.z + a.w * w.w;
        }
    }
    const float bias = isX0 ? __ldg(b0 + j) : __ldg(db + j);
    float* dst = isX0 ? g_X0 : g_Xd;
#pragma unroll
    for (int r = 0; r < 16; ++r) dst[(rt * 16 + r) * 1024 + j] = bias + acc[r];
}

// ============================================================================
// Shared GEMV helper pieces for cluster kernels:
// thread tid: q = tid>>6 (k-slice), lc = tid&63 -> gate g = lc>>4, u0 = (lc&15)*4
// owns 4 gate cols j = g*256 + 64*rank + u0 .. +4 ; partials reduced via smem.
// ============================================================================

// k_enc: cluster of 4 CTAs per batch element; 64 steps of 2-layer LSTM.
__global__ void __launch_bounds__(256) __cluster_dims__(4, 1, 1)
k_enc(const float* __restrict__ b1)
{
    __shared__ __align__(16) float h0[2][256], h1[2][256];
    __shared__ __align__(16) float part[4][256];
    __shared__ __align__(16) float gt[256];
    const int b = blockIdx.x >> 2, rank = blockIdx.x & 3;
    const int tid = threadIdx.x;
    const int q = tid >> 6, lc = tid & 63;
    const int g = lc >> 4, u0 = (lc & 15) * 4;
    const int jb = g * 256 + 64 * rank + u0;       // float4-aligned global col
    const int cl = g * 64 + u0;                    // local col (partials)
    const int jred = (tid >> 6) * 256 + 64 * rank + (tid & 63);  // reduce thread's col
    const float b1j = __ldg(b1 + jred);
    float c0 = 0.f, c1 = 0.f;                      // cell state (threads < 64)

    h0[0][tid] = 0.f; h1[0][tid] = 0.f;
    __syncthreads();

    for (int s = 0; s < 64; ++s) {
        const int p = s & 1;
        // ---------- phase A: layer0 gates (K=256, slice 64 per q) ----------
        {
            const float* hv = &h0[p][64 * q];
            const float4* wp = (const float4*)(g_WT0 + (64 * q) * 1024 + jb);
            float4 acc = make_float4(0.f, 0.f, 0.f, 0.f);
#pragma unroll 8
            for (int k = 0; k < 64; ++k) {
                float h = hv[k];
                float4 w = __ldg(wp); wp += 256;
                acc.x += h * w.x; acc.y += h * w.y; acc.z += h * w.z; acc.w += h * w.w;
            }
            *(float4*)&part[q][cl] = acc;
        }
        __syncthreads();
        gt[tid] = part[0][tid] + part[1][tid] + part[2][tid] + part[3][tid]
                + __ldg(&g_X0[(s * 32 + b) * 1024 + jred]);
        __syncthreads();
        if (tid < 64) {
            const int u = tid;
            float gi = sigf(gt[u]), gf = sigf(gt[64 + u]);
            float gg = tanhf(gt[128 + u]), go = sigf(gt[192 + u]);
            c0 = gf * c0 + gi * gg;
            float hn = go * tanhf(c0);
#pragma unroll
            for (int r = 0; r < 4; ++r) stc(&h0[p ^ 1][64 * rank + u], r, hn);
        }
        csync();
        // ---------- phase B: layer1 gates (K=512: [h0_new ; h1_prev]) ----------
        {
            const float* hv = (q < 2) ? &h0[p ^ 1][128 * q] : &h1[p][128 * (q - 2)];
            const float4* wp = (const float4*)(g_WT1 + (128 * q) * 1024 + jb);
            float4 acc = make_float4(0.f, 0.f, 0.f, 0.f);
#pragma unroll 8
            for (int k = 0; k < 128; ++k) {
                float h = hv[k];
                float4 w = __ldg(wp); wp += 256;
                acc.x += h * w.x; acc.y += h * w.y; acc.z += h * w.z; acc.w += h * w.w;
            }
            *(float4*)&part[q][cl] = acc;
        }
        __syncthreads();
        gt[tid] = part[0][tid] + part[1][tid] + part[2][tid] + part[3][tid] + b1j;
        __syncthreads();
        if (tid < 64) {
            const int u = tid;
            float gi = sigf(gt[u]), gf = sigf(gt[64 + u]);
            float gg = tanhf(gt[128 + u]), go = sigf(gt[192 + u]);
            c1 = gf * c1 + gi * gg;
            float hn = go * tanhf(c1);
#pragma unroll
            for (int r = 0; r < 4; ++r) stc(&h1[p ^ 1][64 * rank + u], r, hn);
            g_enc[(b * 64 + s) * 256 + 64 * rank + u] = hn;
            if (s == 63) g_htop[b * 256 + 64 * rank + u] = hn;
        }
        csync();
    }
}

// k_dec: cluster of 4 CTAs per batch element; 100 steps attention + cell (c_in=0).
__global__ void __launch_bounds__(256) __cluster_dims__(4, 1, 1)
k_dec()
{
    __shared__ __align__(16) float h[2][256], ctx[256];
    __shared__ __align__(16) float part[4][256];
    __shared__ __align__(16) float gt[256];
    __shared__ float sc[64], red[1];
    const int b = blockIdx.x >> 2, rank = blockIdx.x & 3;
    const int tid = threadIdx.x;
    const int q = tid >> 6, lc = tid & 63;
    const int g = lc >> 4, u0 = (lc & 15) * 4;
    const int jb = g * 256 + 64 * rank + u0;
    const int cl = g * 64 + u0;
    const int jred = (tid >> 6) * 256 + 64 * rank + (tid & 63);
    const float* enc = g_enc + b * 64 * 256;

    h[0][tid] = g_htop[b * 256 + tid];
    __syncthreads();

    for (int t = 0; t < 100; ++t) {
        const int p = t & 1;
        // ---- scores[s] = h . enc[s]  (replicated; 4 threads per s) ----
        {
            int s = tid >> 2, qq = tid & 3;
            const float4* er = (const float4*)(enc + s * 256) + qq * 16;
            const float4* hf = (const float4*)(h[p]) + qq * 16;
            float pr = 0.f;
#pragma unroll
            for (int i = 0; i < 16; ++i) {
                float4 e4 = __ldg(er + i); float4 hv = hf[i];
                pr += e4.x * hv.x + e4.y * hv.y + e4.z * hv.z + e4.w * hv.w;
            }
            pr += __shfl_xor_sync(0xffffffffu, pr, 1);
            pr += __shfl_xor_sync(0xffffffffu, pr, 2);
            if (qq == 0) sc[s] = pr;
        }
        __syncthreads();
        if (tid < 32) {
            float s0 = sc[tid], s1 = sc[tid + 32];
            float m = fmaxf(s0, s1);
#pragma unroll
            for (int o = 16; o; o >>= 1) m = fmaxf(m, __shfl_xor_sync(0xffffffffu, m, o));
            float e0 = expf(s0 - m), e1 = expf(s1 - m);
            sc[tid] = e0; sc[tid + 32] = e1;
            float ssum = wred(e0 + e1);
            if (tid == 0) red[0] = 1.f / ssum;
        }
        __syncthreads();
        {
            float a = 0.f;
            const float* ec = enc + tid;
#pragma unroll 8
            for (int s = 0; s < 64; ++s) a += sc[s] * __ldg(ec + s * 256);
            ctx[tid] = a * red[0];
        }
        __syncthreads();
        // ---- gates (K=512: [ctx ; h], slice 128 per q) ----
        {
            const float* hv = (q < 2) ? &ctx[128 * q] : &h[p][128 * (q - 2)];
            const float4* wp = (const float4*)(g_WTd + (128 * q) * 1024 + jb);
            float4 acc = make_float4(0.f, 0.f, 0.f, 0.f);
#pragma unroll 8
            for (int k = 0; k < 128; ++k) {
                float hh = hv[k];
                float4 w = __ldg(wp); wp += 256;
                acc.x += hh * w.x; acc.y += hh * w.y; acc.z += hh * w.z; acc.w += hh * w.w;
            }
            *(float4*)&part[q][cl] = acc;
        }
        __syncthreads();
        gt[tid] = part[0][tid] + part[1][tid] + part[2][tid] + part[3][tid]
                + __ldg(&g_Xd[(t * 32 + b) * 1024 + jred]);
        __syncthreads();
        if (tid < 64) {
            const int u = tid;
            float gi = sigf(gt[u]), gg = tanhf(gt[128 + u]), go = sigf(gt[192 + u]);
            float h2 = go * tanhf(gi * gg);
#pragma unroll
            for (int r = 0; r < 4; ++r) stc(&h[p ^ 1][64 * rank + u], r, h2);
            g_H2[(b * 100 + t) * 256 + 64 * rank + u] = h2;
        }
        csync();
    }
}

// ============================================================================
// k_out: out[r][v] = H2[r].Wout[v] + bout[v]; 128x128x16 tiles, FFMA2.
// ============================================================================
__global__ void __launch_bounds__(256) k_out(const float* __restrict__ Wout,
                                             const float* __restrict__ bout,
                                             float* __restrict__ out)
{
    __shared__ __align__(16) float As[16][132], Bs[16][132];
    const int tid = threadIdx.x;
    const int rb = blockIdx.y * 128, vb = blockIdx.x * 128;
    const int tx = tid & 15, ty = tid >> 4;
    const int r0 = tid >> 2, k0 = (tid & 3) * 4;
    const int r1 = (tid + 256) >> 2, k1 = ((tid + 256) & 3) * 4;

    unsigned long long acc[8][4];
#pragma unroll
    for (int i = 0; i < 8; ++i)
#pragma unroll
        for (int j = 0; j < 4; ++j) acc[i][j] = 0ull;

    const float* A = g_H2;
    float4 a0 = *(const float4*)(A + (rb + r0) * 256 + k0);
    float4 a1 = *(const float4*)(A + (rb + r1) * 256 + k1);
    float4 bv0 = *(const float4*)(Wout + (size_t)(vb + r0) * 256 + k0);
    float4 bv1 = *(const float4*)(Wout + (size_t)(vb + r1) * 256 + k1);

    for (int kc = 0; kc < 16; ++kc) {
        As[k0 + 0][r0] = a0.x; As[k0 + 1][r0] = a0.y; As[k0 + 2][r0] = a0.z; As[k0 + 3][r0] = a0.w;
        As[k1 + 0][r1] = a1.x; As[k1 + 1][r1] = a1.y; As[k1 + 2][r1] = a1.z; As[k1 + 3][r1] = a1.w;
        Bs[k0 + 0][r0] = bv0.x; Bs[k0 + 1][r0] = bv0.y; Bs[k0 + 2][r0] = bv0.z; Bs[k0 + 3][r0] = bv0.w;
        Bs[k1 + 0][r1] = bv1.x; Bs[k1 + 1][r1] = bv1.y; Bs[k1 + 2][r1] = bv1.z; Bs[k1 + 3][r1] = bv1.w;
        __syncthreads();
        if (kc < 15) {
            int kb = (kc + 1) * 16;
            a0 = *(const float4*)(A + (rb + r0) * 256 + kb + k0);
            a1 = *(const float4*)(A + (rb + r1) * 256 + kb + k1);
            bv0 = *(const float4*)(Wout + (size_t)(vb + r0) * 256 + kb + k0);
            bv1 = *(const float4*)(Wout + (size_t)(vb + r1) * 256 + kb + k1);
        }
#pragma unroll
        for (int k = 0; k < 16; ++k) {
            float4 aA = *(const float4*)&As[k][ty * 4];
            float4 aB = *(const float4*)&As[k][ty * 4 + 64];
            float4 bA = *(const float4*)&Bs[k][tx * 4];
            float4 bB = *(const float4*)&Bs[k][tx * 4 + 64];
            unsigned long long bp[4] = { pk2(bA.x, bA.y), pk2(bA.z, bA.w),
                                         pk2(bB.x, bB.y), pk2(bB.z, bB.w) };
            float av[8] = { aA.x, aA.y, aA.z, aA.w, aB.x, aB.y, aB.z, aB.w };
#pragma unroll
            for (int i = 0; i < 8; ++i) {
                unsigned long long ap = pk2(av[i], av[i]);
#pragma unroll
                for (int j = 0; j < 4; ++j) fma2(acc[i][j], ap, bp[j]);
            }
        }
        __syncthreads();
    }

    float bo[8];
#pragma unroll
    for (int j = 0; j < 4; ++j) {
        int cb = ((j >> 1) ? 64 : 0) + tx * 4 + (j & 1) * 2;
        bo[j * 2]     = __ldg(bout + vb + cb);
        bo[j * 2 + 1] = __ldg(bout + vb + cb + 1);
    }
#pragma unroll
    for (int i = 0; i < 8; ++i) {
        int row = rb + ((i < 4) ? (ty * 4 + i) : (64 + ty * 4 + i - 4));
        float* orow = out + (size_t)row * 32000 + vb;
#pragma unroll
        for (int j = 0; j < 4; ++j) {
            int cb = ((j >> 1) ? 64 : 0) + tx * 4 + (j & 1) * 2;
            float lo, hi; upk2(acc[i][j], lo, hi);
            *(float2*)(orow + cb) = make_float2(lo + bo[j * 2], hi + bo[j * 2 + 1]);
        }
    }
}

extern "C" void kernel_launch(void* const* d_in, const int* in_sizes, int n_in,
                              void* d_out, int out_size)
{
    (void)in_sizes; (void)n_in; (void)out_size;
    const int*   qids = (const int*)d_in[0];
    const int*   sids = (const int*)d_in[1];
    const float* encE = (const float*)d_in[2];
    const float* Wih0 = (const float*)d_in[3];
    const float* Whh0 = (const float*)d_in[4];
    const float* b0   = (const float*)d_in[5];
    const float* Wih1 = (const float*)d_in[6];
    const float* Whh1 = (const float*)d_in[7];
    const float* b1   = (const float*)d_in[8];
    const float* decE = (const float*)d_in[9];
    const float* dWih = (const float*)d_in[10];
    const float* dWhh = (const float*)d_in[11];
    const float* db   = (const float*)d_in[12];
    const float* Wout = (const float*)d_in[13];
    const float* bout = (const float*)d_in[14];
    float* out = (float*)d_out;

    k_tr<<<1280, 256>>>(Whh0, Wih1, Whh1, dWih, dWhh);
    k_pre<<<1312, 256>>>(qids, sids, encE, Wih0, b0, decE, dWih, db);
    k_enc<<<128, 256>>>(b1);
    k_dec<<<128, 256>>>();
    k_out<<<dim3(250, 25), 256>>>(Wout, bout, out);
}

// round 9
// speedup vs baseline: 3.5363x; 1.2015x over previous
#include <cuda_runtime.h>
#include <math.h>

// Scratch (device globals -- no runtime allocation allowed)
__device__ float g_X0[2048 * 1024];   // enc layer0 input gates  [s*32+b][j]
__device__ float g_Xd[3200 * 1024];   // dec input gates         [t*32+b][j]
__device__ float g_enc[32 * 64 * 256];// enc_out [b][s][h]
__device__ float g_htop[32 * 256];    // final top-layer h
__device__ float g_H2[3200 * 256];    // decoder hiddens [b*100+t][h]
// transposed weights [k][j] for broadcast-FMA GEMVs
__device__ float g_WT0[256 * 1024];   // Whh0^T
__device__ float g_WT1[512 * 1024];   // [Wih1 ; Whh1]^T
__device__ float g_WTd[512 * 1024];   // [dWih[:,128:384] ; dWhh]^T

__device__ __forceinline__ float sigf(float x) { return 1.f / (1.f + expf(-x)); }

__device__ __forceinline__ float wred(float v) {
#pragma unroll
    for (int o = 16; o; o >>= 1) v += __shfl_xor_sync(0xffffffffu, v, o);
    return v;
}

// DSMEM store: write v to the same smem offset in cluster CTA `rank`
__device__ __forceinline__ void stc(float* p, int rank, float v) {
    unsigned a = (unsigned)__cvta_generic_to_shared(p);
    unsigned r;
    asm volatile("mapa.shared::cluster.u32 %0, %1, %2;" : "=r"(r) : "r"(a), "r"(rank));
    asm volatile("st.shared::cluster.f32 [%0], %1;" :: "r"(r), "f"(v) : "memory");
}
__device__ __forceinline__ void csync() {
    asm volatile("barrier.cluster.arrive.aligned;" ::: "memory");
    asm volatile("barrier.cluster.wait.aligned;" ::: "memory");
}

// packed f32x2 FMA (sm_100+ PTX)
__device__ __forceinline__ unsigned long long pk2(float lo, float hi) {
    unsigned long long r;
    asm("mov.b64 %0, {%1,%2};" : "=l"(r) : "f"(lo), "f"(hi));
    return r;
}
__device__ __forceinline__ void fma2(unsigned long long& d, unsigned long long a,
                                     unsigned long long b) {
    asm("fma.rn.f32x2 %0, %1, %2, %0;" : "+l"(d) : "l"(a), "l"(b));
}
__device__ __forceinline__ void upk2(unsigned long long v, float& lo, float& hi) {
    asm("mov.b64 {%0,%1}, %2;" : "=f"(lo), "=f"(hi) : "l"(v));
}

// ============================================================================
// k_tr: transpose recurrent weights into [k][j] layout (1280 rows of 1024)
// ============================================================================
__global__ void k_tr(const float* __restrict__ Whh0, const float* __restrict__ Wih1,
                     const float* __restrict__ Whh1, const float* __restrict__ dWih,
                     const float* __restrict__ dWhh)
{
    const int row = blockIdx.x;
    const int j0 = threadIdx.x * 4;
    const float* src; long stride; float* dst; int k;
    if (row < 256) {
        k = row; src = Whh0 + k; stride = 256; dst = g_WT0 + k * 1024;
    } else if (row < 768) {
        k = row - 256;
        src = (k < 256) ? (Wih1 + k) : (Whh1 + (k - 256));
        stride = 256; dst = g_WT1 + k * 1024;
    } else {
        k = row - 768;
        if (k < 256) { src = dWih + 128 + k; stride = 384; }
        else         { src = dWhh + (k - 256); stride = 256; }
        dst = g_WTd + k * 1024;
    }
    float4 v;
    v.x = __ldg(src + (long)(j0 + 0) * stride);
    v.y = __ldg(src + (long)(j0 + 1) * stride);
    v.z = __ldg(src + (long)(j0 + 2) * stride);
    v.w = __ldg(src + (long)(j0 + 3) * stride);
    *(float4*)(dst + j0) = v;
}

// ============================================================================
// k_pre: X0[r][j] = b0[j] + emb(q)[r].Wih0[j]; Xd[r][j] = db[j] + emb(d)[r].dWih[j][0:128]
// ============================================================================
__global__ void k_pre(const int* __restrict__ qids, const int* __restrict__ sids,
                      const float* __restrict__ encE, const float* __restrict__ Wih0,
                      const float* __restrict__ b0, const float* __restrict__ decE,
                      const float* __restrict__ dWih, const float* __restrict__ db)
{
    __shared__ __align__(16) float4 a_s[16 * 32];
    const int blk = blockIdx.x, tid = threadIdx.x;
    const bool isX0 = blk < 512;
    const int u = isX0 ? blk : blk - 512;
    const int rt = u >> 2, jb = (u & 3) << 8;
    const float4* Ef = (const float4*)(isX0 ? encE : decE);
#pragma unroll
    for (int i = 0; i < 2; ++i) {
        int lin = tid + i * 256;
        int rr = lin >> 5, e4 = lin & 31;
        int row = rt * 16 + rr, b = row & 31, idx = row >> 5;
        int tok = isX0 ? qids[b * 64 + idx] : (idx == 0 ? 1 : sids[b * 100 + idx - 1]);
        a_s[rr * 32 + e4] = Ef[(size_t)tok * 32 + e4];
    }
    __syncthreads();
    const int j = jb + tid;
    const float4* Wf = (const float4*)(isX0 ? (Wih0 + j * 128) : (dWih + j * 384));
    float acc[16];
#pragma unroll
    for (int r = 0; r < 16; ++r) acc[r] = 0.f;
#pragma unroll 4
    for (int e4 = 0; e4 < 32; ++e4) {
        float4 w = __ldg(Wf + e4);
#pragma unroll
        for (int r = 0; r < 16; ++r) {
            float4 a = a_s[r * 32 + e4];
            acc[r] += a.x * w.x + a.y * w.y + a.z * w.z + a.w * w.w;
        }
    }
    const float bias = isX0 ? __ldg(b0 + j) : __ldg(db + j);
    float* dst = isX0 ? g_X0 : g_Xd;
#pragma unroll
    for (int r = 0; r < 16; ++r) dst[(rt * 16 + r) * 1024 + j] = bias + acc[r];
}

// ============================================================================
// Cluster kernels, 512 threads: q = tid>>6 (8 k-slices), lc = tid&63 ->
// gate g = lc>>4, u0 = (lc&15)*4; thread owns 4 gate cols
// j = g*256 + 64*rank + u0.  8-way smem partial reduction.
// ============================================================================

// k_enc: cluster of 4 CTAs per batch element; 64 steps of 2-layer LSTM.
__global__ void __launch_bounds__(512) __cluster_dims__(4, 1, 1)
k_enc(const float* __restrict__ b1)
{
    __shared__ __align__(16) float h0[2][256], h1[2][256];
    __shared__ __align__(16) float part[8][256];
    __shared__ __align__(16) float gt[256];
    const int b = blockIdx.x >> 2, rank = blockIdx.x & 3;
    const int tid = threadIdx.x;
    const int q = tid >> 6, lc = tid & 63;
    const int g = lc >> 4, u0 = (lc & 15) * 4;
    const int jb = g * 256 + 64 * rank + u0;       // global gate col (float4-aligned)
    const int cl = g * 64 + u0;                    // local col (partials)
    const int jred = (tid >> 6) * 256 + 64 * rank + (tid & 63);  // valid for tid<256
    const float b1j = (tid < 256) ? __ldg(b1 + jred) : 0.f;
    float c0 = 0.f, c1 = 0.f;                      // cell state (threads < 64)

    if (tid < 256) { h0[0][tid] = 0.f; h1[0][tid] = 0.f; }
    __syncthreads();

    for (int s = 0; s < 64; ++s) {
        const int p = s & 1;
        // ---------- phase A: layer0 gates (K=256, 32 k per slice) ----------
        {
            const float* hv = &h0[p][32 * q];
            const float4* wp = (const float4*)(g_WT0 + (32 * q) * 1024 + jb);
            float4 acc = make_float4(0.f, 0.f, 0.f, 0.f);
#pragma unroll 8
            for (int k = 0; k < 32; ++k) {
                float h = hv[k];
                float4 w = __ldg(wp); wp += 256;
                acc.x += h * w.x; acc.y += h * w.y; acc.z += h * w.z; acc.w += h * w.w;
            }
            *(float4*)&part[q][cl] = acc;
        }
        __syncthreads();
        if (tid < 256) {
            float sum = part[0][tid] + part[1][tid] + part[2][tid] + part[3][tid]
                      + part[4][tid] + part[5][tid] + part[6][tid] + part[7][tid];
            gt[tid] = sum + __ldg(&g_X0[(s * 32 + b) * 1024 + jred]);
        }
        __syncthreads();
        if (tid < 64) {
            const int u = tid;
            float gi = sigf(gt[u]), gf = sigf(gt[64 + u]);
            float gg = tanhf(gt[128 + u]), go = sigf(gt[192 + u]);
            c0 = gf * c0 + gi * gg;
            float hn = go * tanhf(c0);
#pragma unroll
            for (int r = 0; r < 4; ++r) stc(&h0[p ^ 1][64 * rank + u], r, hn);
        }
        csync();
        // ---------- phase B: layer1 gates (K=512: [h0_new ; h1_prev], 64 k/slice) ----------
        {
            const float* hv = (q < 4) ? &h0[p ^ 1][64 * q] : &h1[p][64 * (q - 4)];
            const float4* wp = (const float4*)(g_WT1 + (64 * q) * 1024 + jb);
            float4 acc = make_float4(0.f, 0.f, 0.f, 0.f);
#pragma unroll 8
            for (int k = 0; k < 64; ++k) {
                float h = hv[k];
                float4 w = __ldg(wp); wp += 256;
                acc.x += h * w.x; acc.y += h * w.y; acc.z += h * w.z; acc.w += h * w.w;
            }
            *(float4*)&part[q][cl] = acc;
        }
        __syncthreads();
        if (tid < 256) {
            float sum = part[0][tid] + part[1][tid] + part[2][tid] + part[3][tid]
                      + part[4][tid] + part[5][tid] + part[6][tid] + part[7][tid];
            gt[tid] = sum + b1j;
        }
        __syncthreads();
        if (tid < 64) {
            const int u = tid;
            float gi = sigf(gt[u]), gf = sigf(gt[64 + u]);
            float gg = tanhf(gt[128 + u]), go = sigf(gt[192 + u]);
            c1 = gf * c1 + gi * gg;
            float hn = go * tanhf(c1);
#pragma unroll
            for (int r = 0; r < 4; ++r) stc(&h1[p ^ 1][64 * rank + u], r, hn);
            g_enc[(b * 64 + s) * 256 + 64 * rank + u] = hn;
            if (s == 63) g_htop[b * 256 + 64 * rank + u] = hn;
        }
        csync();
    }
}

// k_dec: cluster of 4 CTAs per batch element; 100 steps attention + cell (c_in=0).
__global__ void __launch_bounds__(512) __cluster_dims__(4, 1, 1)
k_dec()
{
    __shared__ __align__(16) float h[2][256], ctx[256];
    __shared__ __align__(16) float part[8][256];
    __shared__ __align__(16) float pc[2][256];
    __shared__ __align__(16) float gt[256];
    __shared__ float sc[64], red[1];
    const int b = blockIdx.x >> 2, rank = blockIdx.x & 3;
    const int tid = threadIdx.x;
    const int q = tid >> 6, lc = tid & 63;
    const int g = lc >> 4, u0 = (lc & 15) * 4;
    const int jb = g * 256 + 64 * rank + u0;
    const int cl = g * 64 + u0;
    const int jred = (tid >> 6) * 256 + 64 * rank + (tid & 63);  // valid tid<256
    const float* enc = g_enc + b * 64 * 256;

    if (tid < 256) h[0][tid] = g_htop[b * 256 + tid];
    __syncthreads();

    for (int t = 0; t < 100; ++t) {
        const int p = t & 1;
        // ---- scores[s] = h . enc[s]  (8 threads per s, 32 floats each) ----
        {
            int s = tid >> 3, qq = tid & 7;
            const float4* er = (const float4*)(enc + s * 256) + qq * 8;
            const float4* hf = (const float4*)(h[p]) + qq * 8;
            float pr = 0.f;
#pragma unroll
            for (int i = 0; i < 8; ++i) {
                float4 e4 = __ldg(er + i); float4 hv = hf[i];
                pr += e4.x * hv.x + e4.y * hv.y + e4.z * hv.z + e4.w * hv.w;
            }
            pr += __shfl_xor_sync(0xffffffffu, pr, 1);
            pr += __shfl_xor_sync(0xffffffffu, pr, 2);
            pr += __shfl_xor_sync(0xffffffffu, pr, 4);
            if (qq == 0) sc[s] = pr;
        }
        __syncthreads();
        if (tid < 32) {
            float s0 = sc[tid], s1 = sc[tid + 32];
            float m = fmaxf(s0, s1);
#pragma unroll
            for (int o = 16; o; o >>= 1) m = fmaxf(m, __shfl_xor_sync(0xffffffffu, m, o));
            float e0 = expf(s0 - m), e1 = expf(s1 - m);
            sc[tid] = e0; sc[tid + 32] = e1;
            float ssum = wred(e0 + e1);
            if (tid == 0) red[0] = 1.f / ssum;
        }
        __syncthreads();
        // ---- ctx: split s into two halves across the 512 threads ----
        {
            int k = tid & 255, half = tid >> 8;
            float a = 0.f;
            const float* ec = enc + 32 * half * 256 + k;
#pragma unroll 8
            for (int s = 0; s < 32; ++s) a += sc[32 * half + s] * __ldg(ec + s * 256);
            pc[half][k] = a;
        }
        __syncthreads();
        if (tid < 256) ctx[tid] = (pc[0][tid] + pc[1][tid]) * red[0];
        __syncthreads();
        // ---- gates (K=512: [ctx ; h], 64 k per slice) ----
        {
            const float* hv = (q < 4) ? &ctx[64 * q] : &h[p][64 * (q - 4)];
            const float4* wp = (const float4*)(g_WTd + (64 * q) * 1024 + jb);
            float4 acc = make_float4(0.f, 0.f, 0.f, 0.f);
#pragma unroll 8
            for (int k = 0; k < 64; ++k) {
                float hh = hv[k];
                float4 w = __ldg(wp); wp += 256;
                acc.x += hh * w.x; acc.y += hh * w.y; acc.z += hh * w.z; acc.w += hh * w.w;
            }
            *(float4*)&part[q][cl] = acc;
        }
        __syncthreads();
        if (tid < 256) {
            float sum = part[0][tid] + part[1][tid] + part[2][tid] + part[3][tid]
                      + part[4][tid] + part[5][tid] + part[6][tid] + part[7][tid];
            gt[tid] = sum + __ldg(&g_Xd[(t * 32 + b) * 1024 + jred]);
        }
        __syncthreads();
        if (tid < 64) {
            const int u = tid;
            float gi = sigf(gt[u]), gg = tanhf(gt[128 + u]), go = sigf(gt[192 + u]);
            float h2 = go * tanhf(gi * gg);
#pragma unroll
            for (int r = 0; r < 4; ++r) stc(&h[p ^ 1][64 * rank + u], r, h2);
            g_H2[(b * 100 + t) * 256 + 64 * rank + u] = h2;
        }
        csync();
    }
}

// ============================================================================
// k_out: out[r][v] = H2[r].Wout[v] + bout[v]; 128x128x16 tiles, FFMA2.
// ============================================================================
__global__ void __launch_bounds__(256) k_out(const float* __restrict__ Wout,
                                             const float* __restrict__ bout,
                                             float* __restrict__ out)
{
    __shared__ __align__(16) float As[16][132], Bs[16][132];
    const int tid = threadIdx.x;
    const int rb = blockIdx.y * 128, vb = blockIdx.x * 128;
    const int tx = tid & 15, ty = tid >> 4;
    const int r0 = tid >> 2, k0 = (tid & 3) * 4;
    const int r1 = (tid + 256) >> 2, k1 = ((tid + 256) & 3) * 4;

    unsigned long long acc[8][4];
#pragma unroll
    for (int i = 0; i < 8; ++i)
#pragma unroll
        for (int j = 0; j < 4; ++j) acc[i][j] = 0ull;

    const float* A = g_H2;
    float4 a0 = *(const float4*)(A + (rb + r0) * 256 + k0);
    float4 a1 = *(const float4*)(A + (rb + r1) * 256 + k1);
    float4 bv0 = *(const float4*)(Wout + (size_t)(vb + r0) * 256 + k0);
    float4 bv1 = *(const float4*)(Wout + (size_t)(vb + r1) * 256 + k1);

    for (int kc = 0; kc < 16; ++kc) {
        As[k0 + 0][r0] = a0.x; As[k0 + 1][r0] = a0.y; As[k0 + 2][r0] = a0.z; As[k0 + 3][r0] = a0.w;
        As[k1 + 0][r1] = a1.x; As[k1 + 1][r1] = a1.y; As[k1 + 2][r1] = a1.z; As[k1 + 3][r1] = a1.w;
        Bs[k0 + 0][r0] = bv0.x; Bs[k0 + 1][r0] = bv0.y; Bs[k0 + 2][r0] = bv0.z; Bs[k0 + 3][r0] = bv0.w;
        Bs[k1 + 0][r1] = bv1.x; Bs[k1 + 1][r1] = bv1.y; Bs[k1 + 2][r1] = bv1.z; Bs[k1 + 3][r1] = bv1.w;
        __syncthreads();
        if (kc < 15) {
            int kb = (kc + 1) * 16;
            a0 = *(const float4*)(A + (rb + r0) * 256 + kb + k0);
            a1 = *(const float4*)(A + (rb + r1) * 256 + kb + k1);
            bv0 = *(const float4*)(Wout + (size_t)(vb + r0) * 256 + kb + k0);
            bv1 = *(const float4*)(Wout + (size_t)(vb + r1) * 256 + kb + k1);
        }
#pragma unroll
        for (int k = 0; k < 16; ++k) {
            float4 aA = *(const float4*)&As[k][ty * 4];
            float4 aB = *(const float4*)&As[k][ty * 4 + 64];
            float4 bA = *(const float4*)&Bs[k][tx * 4];
            float4 bB = *(const float4*)&Bs[k][tx * 4 + 64];
            unsigned long long bp[4] = { pk2(bA.x, bA.y), pk2(bA.z, bA.w),
                                         pk2(bB.x, bB.y), pk2(bB.z, bB.w) };
            float av[8] = { aA.x, aA.y, aA.z, aA.w, aB.x, aB.y, aB.z, aB.w };
#pragma unroll
            for (int i = 0; i < 8; ++i) {
                unsigned long long ap = pk2(av[i], av[i]);
#pragma unroll
                for (int j = 0; j < 4; ++j) fma2(acc[i][j], ap, bp[j]);
            }
        }
        __syncthreads();
    }

    float bo[8];
#pragma unroll
    for (int j = 0; j < 4; ++j) {
        int cb = ((j >> 1) ? 64 : 0) + tx * 4 + (j & 1) * 2;
        bo[j * 2]     = __ldg(bout + vb + cb);
        bo[j * 2 + 1] = __ldg(bout + vb + cb + 1);
    }
#pragma unroll
    for (int i = 0; i < 8; ++i) {
        int row = rb + ((i < 4) ? (ty * 4 + i) : (64 + ty * 4 + i - 4));
        float* orow = out + (size_t)row * 32000 + vb;
#pragma unroll
        for (int j = 0; j < 4; ++j) {
            int cb = ((j >> 1) ? 64 : 0) + tx * 4 + (j & 1) * 2;
            float lo, hi; upk2(acc[i][j], lo, hi);
            *(float2*)(orow + cb) = make_float2(lo + bo[j * 2], hi + bo[j * 2 + 1]);
        }
    }
}

extern "C" void kernel_launch(void* const* d_in, const int* in_sizes, int n_in,
                              void* d_out, int out_size)
{
    (void)in_sizes; (void)n_in; (void)out_size;
    const int*   qids = (const int*)d_in[0];
    const int*   sids = (const int*)d_in[1];
    const float* encE = (const float*)d_in[2];
    const float* Wih0 = (const float*)d_in[3];
    const float* Whh0 = (const float*)d_in[4];
    const float* b0   = (const float*)d_in[5];
    const float* Wih1 = (const float*)d_in[6];
    const float* Whh1 = (const float*)d_in[7];
    const float* b1   = (const float*)d_in[8];
    const float* decE = (const float*)d_in[9];
    const float* dWih = (const float*)d_in[10];
    const float* dWhh = (const float*)d_in[11];
    const float* db   = (const float*)d_in[12];
    const float* Wout = (const float*)d_in[13];
    const float* bout = (const float*)d_in[14];
    float* out = (float*)d_out;

    k_tr<<<1280, 256>>>(Whh0, Wih1, Whh1, dWih, dWhh);
    k_pre<<<1312, 256>>>(qids, sids, encE, Wih0, b0, decE, dWih, db);
    k_enc<<<128, 512>>>(b1);
    k_dec<<<128, 512>>>();
    k_out<<<dim3(250, 25), 256>>>(Wout, bout, out);
}

// round 10
// speedup vs baseline: 3.9868x; 1.1274x over previous
#include <cuda_runtime.h>
#include <math.h>

// Scratch (device globals -- no runtime allocation allowed)
__device__ float g_X0[2048 * 1024];   // enc layer0 input gates  [s*32+b][j]
__device__ float g_Xd[3200 * 1024];   // dec input gates         [t*32+b][j]
__device__ float g_enc[32 * 64 * 256];// enc_out [b][s][h]
__device__ float g_htop[32 * 256];    // final top-layer h
__device__ float g_H2[3200 * 256];    // decoder hiddens [b*100+t][h]
// transposed weights [k][j] for broadcast-FMA GEMVs
__device__ float g_WT0[256 * 1024];   // Whh0^T
__device__ float g_WT1[512 * 1024];   // [Wih1 ; Whh1]^T
__device__ float g_WTd[512 * 1024];   // [dWih[:,128:384] ; dWhh]^T

__device__ __forceinline__ float sigf(float x) { return 1.f / (1.f + expf(-x)); }

__device__ __forceinline__ float wred(float v) {
#pragma unroll
    for (int o = 16; o; o >>= 1) v += __shfl_xor_sync(0xffffffffu, v, o);
    return v;
}

// DSMEM store: write v to the same smem offset in cluster CTA `rank`
__device__ __forceinline__ void stc(float* p, int rank, float v) {
    unsigned a = (unsigned)__cvta_generic_to_shared(p);
    unsigned r;
    asm volatile("mapa.shared::cluster.u32 %0, %1, %2;" : "=r"(r) : "r"(a), "r"(rank));
    asm volatile("st.shared::cluster.f32 [%0], %1;" :: "r"(r), "f"(v) : "memory");
}
__device__ __forceinline__ void csync() {
    asm volatile("barrier.cluster.arrive.aligned;" ::: "memory");
    asm volatile("barrier.cluster.wait.aligned;" ::: "memory");
}

// packed f32x2 FMA (sm_100+ PTX)
__device__ __forceinline__ unsigned long long pk2(float lo, float hi) {
    unsigned long long r;
    asm("mov.b64 %0, {%1,%2};" : "=l"(r) : "f"(lo), "f"(hi));
    return r;
}
__device__ __forceinline__ void fma2(unsigned long long& d, unsigned long long a,
                                     unsigned long long b) {
    asm("fma.rn.f32x2 %0, %1, %2, %0;" : "+l"(d) : "l"(a), "l"(b));
}
__device__ __forceinline__ void upk2(unsigned long long v, float& lo, float& hi) {
    asm("mov.b64 {%0,%1}, %2;" : "=f"(lo), "=f"(hi) : "l"(v));
}

// ============================================================================
// k_tr: transpose recurrent weights into [k][j] layout (1280 rows of 1024)
// ============================================================================
__global__ void k_tr(const float* __restrict__ Whh0, const float* __restrict__ Wih1,
                     const float* __restrict__ Whh1, const float* __restrict__ dWih,
                     const float* __restrict__ dWhh)
{
    const int row = blockIdx.x;
    const int j0 = threadIdx.x * 4;
    const float* src; long stride; float* dst; int k;
    if (row < 256) {
        k = row; src = Whh0 + k; stride = 256; dst = g_WT0 + k * 1024;
    } else if (row < 768) {
        k = row - 256;
        src = (k < 256) ? (Wih1 + k) : (Whh1 + (k - 256));
        stride = 256; dst = g_WT1 + k * 1024;
    } else {
        k = row - 768;
        if (k < 256) { src = dWih + 128 + k; stride = 384; }
        else         { src = dWhh + (k - 256); stride = 256; }
        dst = g_WTd + k * 1024;
    }
    float4 v;
    v.x = __ldg(src + (long)(j0 + 0) * stride);
    v.y = __ldg(src + (long)(j0 + 1) * stride);
    v.z = __ldg(src + (long)(j0 + 2) * stride);
    v.w = __ldg(src + (long)(j0 + 3) * stride);
    *(float4*)(dst + j0) = v;
}

// ============================================================================
// k_pre: X0[r][j] = b0[j] + emb(q)[r].Wih0[j]; Xd[r][j] = db[j] + emb(d)[r].dWih[j][0:128]
// ============================================================================
__global__ void k_pre(const int* __restrict__ qids, const int* __restrict__ sids,
                      const float* __restrict__ encE, const float* __restrict__ Wih0,
                      const float* __restrict__ b0, const float* __restrict__ decE,
                      const float* __restrict__ dWih, const float* __restrict__ db)
{
    __shared__ __align__(16) float4 a_s[16 * 32];
    const int blk = blockIdx.x, tid = threadIdx.x;
    const bool isX0 = blk < 512;
    const int u = isX0 ? blk : blk - 512;
    const int rt = u >> 2, jb = (u & 3) << 8;
    const float4* Ef = (const float4*)(isX0 ? encE : decE);
#pragma unroll
    for (int i = 0; i < 2; ++i) {
        int lin = tid + i * 256;
        int rr = lin >> 5, e4 = lin & 31;
        int row = rt * 16 + rr, b = row & 31, idx = row >> 5;
        int tok = isX0 ? qids[b * 64 + idx] : (idx == 0 ? 1 : sids[b * 100 + idx - 1]);
        a_s[rr * 32 + e4] = Ef[(size_t)tok * 32 + e4];
    }
    __syncthreads();
    const int j = jb + tid;
    const float4* Wf = (const float4*)(isX0 ? (Wih0 + j * 128) : (dWih + j * 384));
    float acc[16];
#pragma unroll
    for (int r = 0; r < 16; ++r) acc[r] = 0.f;
#pragma unroll 4
    for (int e4 = 0; e4 < 32; ++e4) {
        float4 w = __ldg(Wf + e4);
#pragma unroll
        for (int r = 0; r < 16; ++r) {
            float4 a = a_s[r * 32 + e4];
            acc[r] += a.x * w.x + a.y * w.y + a.z * w.z + a.w * w.w;
        }
    }
    const float bias = isX0 ? __ldg(b0 + j) : __ldg(db + j);
    float* dst = isX0 ? g_X0 : g_Xd;
#pragma unroll
    for (int r = 0; r < 16; ++r) dst[(rt * 16 + r) * 1024 + j] = bias + acc[r];
}

// ============================================================================
// Cluster-8 recurrence, 2 batch elements per cluster packed in f32x2 lanes.
// 16 clusters x 8 CTAs = 128 CTAs, 512 threads.
// rank owns units [32*rank, 32*rank+32) -> 128 gate cols (4 gates x 32 u).
// Gate GEMV: q = tid>>5 (16 k-slices), cg = tid&31 -> 4 cols (float4 group):
//   g = cg>>3, colf4 = g*64 + 8*rank + (cg&7).
// Inner loop: LDS.64 h-pair (broadcast) + LDG.128 weights + 4x FFMA2.
// 16-slice partials reduced in smem; cell by threads<64 (bh = tid>>5, u = tid&31);
// new h broadcast to all 8 ranks via st.shared::cluster + cluster barrier.
// ============================================================================

__global__ void __launch_bounds__(512) __cluster_dims__(8, 1, 1)
k_enc(const float* __restrict__ b1)
{
    __shared__ __align__(16) float2 H0[2][256], H1[2][256];
    __shared__ __align__(16) float2 part[16][128];
    __shared__ __align__(16) float2 gt[128];
    const int cid = blockIdx.x >> 3, rank = blockIdx.x & 7;
    const int b0 = 2 * cid;
    const int tid = threadIdx.x;
    const int q = tid >> 5, cg = tid & 31;
    const int colf4 = (cg >> 3) * 64 + 8 * rank + (cg & 7);
    const int jg = (tid >> 5) * 256 + 32 * rank + (tid & 31);   // valid tid<128
    float c0 = 0.f, c1 = 0.f;                                   // cells (tid<64)
    float bias1 = (tid < 128) ? __ldg(b1 + jg) : 0.f;

    if (tid < 256) { H0[0][tid] = make_float2(0.f, 0.f); H1[0][tid] = make_float2(0.f, 0.f); }
    __syncthreads();

    for (int s = 0; s < 64; ++s) {
        const int p = s & 1;
        float xa = 0.f, xb = 0.f;
        if (tid < 128) {
            xa = __ldg(&g_X0[(s * 32 + b0) * 1024 + jg]);
            xb = __ldg(&g_X0[(s * 32 + b0 + 1) * 1024 + jg]);
        }
        // ---- L0 gates: K=256, 16 k per slice ----
        {
            const unsigned long long* hv = (const unsigned long long*)&H0[p][16 * q];
            const float4* wp = (const float4*)g_WT0 + (16 * q) * 256 + colf4;
            unsigned long long a0 = 0, a1 = 0, a2 = 0, a3 = 0;
#pragma unroll
            for (int k = 0; k < 16; ++k) {
                unsigned long long hp = hv[k];
                float4 w = __ldg(wp); wp += 256;
                fma2(a0, hp, pk2(w.x, w.x));
                fma2(a1, hp, pk2(w.y, w.y));
                fma2(a2, hp, pk2(w.z, w.z));
                fma2(a3, hp, pk2(w.w, w.w));
            }
            unsigned long long* pr = (unsigned long long*)&part[q][cg * 4];
            pr[0] = a0; pr[1] = a1; pr[2] = a2; pr[3] = a3;
        }
        __syncthreads();
        if (tid < 128) {
            float sx = xa, sy = xb;
#pragma unroll
            for (int qq = 0; qq < 16; ++qq) { float2 v = part[qq][tid]; sx += v.x; sy += v.y; }
            gt[tid] = make_float2(sx, sy);
        }
        __syncthreads();
        if (tid < 64) {
            int bh = tid >> 5, un = tid & 31;
            float gi_ = bh ? gt[un].y : gt[un].x;
            float gf_ = bh ? gt[32 + un].y : gt[32 + un].x;
            float gg_ = bh ? gt[64 + un].y : gt[64 + un].x;
            float go_ = bh ? gt[96 + un].y : gt[96 + un].x;
            c0 = sigf(gf_) * c0 + sigf(gi_) * tanhf(gg_);
            float hn = sigf(go_) * tanhf(c0);
            float* dst = ((float*)&H0[p ^ 1][32 * rank + un]) + bh;
#pragma unroll
            for (int r = 0; r < 8; ++r) stc(dst, r, hn);
        }
        csync();
        // ---- L1 gates: K=512 = [H0[p^1] ; H1[p]], 32 k per slice ----
        {
            const unsigned long long* hv = (q < 8)
                ? (const unsigned long long*)&H0[p ^ 1][32 * q]
                : (const unsigned long long*)&H1[p][32 * (q - 8)];
            const float4* wp = (const float4*)g_WT1 + (32 * q) * 256 + colf4;
            unsigned long long a0 = 0, a1 = 0, a2 = 0, a3 = 0;
#pragma unroll
            for (int k = 0; k < 32; ++k) {
                unsigned long long hp = hv[k];
                float4 w = __ldg(wp); wp += 256;
                fma2(a0, hp, pk2(w.x, w.x));
                fma2(a1, hp, pk2(w.y, w.y));
                fma2(a2, hp, pk2(w.z, w.z));
                fma2(a3, hp, pk2(w.w, w.w));
            }
            unsigned long long* pr = (unsigned long long*)&part[q][cg * 4];
            pr[0] = a0; pr[1] = a1; pr[2] = a2; pr[3] = a3;
        }
        __syncthreads();
        if (tid < 128) {
            float sx = bias1, sy = bias1;
#pragma unroll
            for (int qq = 0; qq < 16; ++qq) { float2 v = part[qq][tid]; sx += v.x; sy += v.y; }
            gt[tid] = make_float2(sx, sy);
        }
        __syncthreads();
        if (tid < 64) {
            int bh = tid >> 5, un = tid & 31;
            float gi_ = bh ? gt[un].y : gt[un].x;
            float gf_ = bh ? gt[32 + un].y : gt[32 + un].x;
            float gg_ = bh ? gt[64 + un].y : gt[64 + un].x;
            float go_ = bh ? gt[96 + un].y : gt[96 + un].x;
            c1 = sigf(gf_) * c1 + sigf(gi_) * tanhf(gg_);
            float hn = sigf(go_) * tanhf(c1);
            float* dst = ((float*)&H1[p ^ 1][32 * rank + un]) + bh;
#pragma unroll
            for (int r = 0; r < 8; ++r) stc(dst, r, hn);
            g_enc[((b0 + bh) * 64 + s) * 256 + 32 * rank + un] = hn;
            if (s == 63) g_htop[(b0 + bh) * 256 + 32 * rank + un] = hn;
        }
        csync();
    }
}

__global__ void __launch_bounds__(512) __cluster_dims__(8, 1, 1)
k_dec()
{
    __shared__ __align__(16) float2 Hd[2][256], Ctx[256];
    __shared__ __align__(16) float2 part[16][128];
    __shared__ __align__(16) float2 gt[128];
    __shared__ float sc[2][64];
    __shared__ float rz[2];
    const int cid = blockIdx.x >> 3, rank = blockIdx.x & 7;
    const int b0 = 2 * cid;
    const int tid = threadIdx.x;
    const int q = tid >> 5, cg = tid & 31;
    const int colf4 = (cg >> 3) * 64 + 8 * rank + (cg & 7);
    const int jg = (tid >> 5) * 256 + 32 * rank + (tid & 31);   // valid tid<128

    if (tid < 256)
        Hd[0][tid] = make_float2(g_htop[b0 * 256 + tid], g_htop[(b0 + 1) * 256 + tid]);
    __syncthreads();

    for (int t = 0; t < 100; ++t) {
        const int p = t & 1;
        float xa = 0.f, xb = 0.f;
        if (tid < 128) {
            xa = __ldg(&g_Xd[(t * 32 + b0) * 1024 + jg]);
            xb = __ldg(&g_Xd[(t * 32 + b0 + 1) * 1024 + jg]);
        }
        // ---- scores: rank owns s in [8*rank, 8*rank+8); warp per (bh, s) ----
        {
            int bh = tid >> 8;
            int sl = (tid >> 5) & 7;
            int l = tid & 31;
            int s = 8 * rank + sl;
            const float4* er = (const float4*)(g_enc + ((b0 + bh) * 64 + s) * 256) + l * 2;
            float4 e0 = __ldg(er), e1 = __ldg(er + 1);
            const float2* hp = &Hd[p][l * 8];
            float h0_ = bh ? hp[0].y : hp[0].x, h1_ = bh ? hp[1].y : hp[1].x;
            float h2_ = bh ? hp[2].y : hp[2].x, h3_ = bh ? hp[3].y : hp[3].x;
            float h4_ = bh ? hp[4].y : hp[4].x, h5_ = bh ? hp[5].y : hp[5].x;
            float h6_ = bh ? hp[6].y : hp[6].x, h7_ = bh ? hp[7].y : hp[7].x;
            float pr = e0.x * h0_ + e0.y * h1_ + e0.z * h2_ + e0.w * h3_
                     + e1.x * h4_ + e1.y * h5_ + e1.z * h6_ + e1.w * h7_;
            pr = wred(pr);
            if (l == 0) {
#pragma unroll
                for (int r = 0; r < 8; ++r) stc(&sc[bh][s], r, pr);
            }
        }
        csync();
        // ---- softmax (warp 0 -> b0, warp 1 -> b1), replicated per CTA ----
        if (tid < 64) {
            int bh = tid >> 5, l = tid & 31;
            float s0 = sc[bh][l], s1 = sc[bh][l + 32];
            float m = fmaxf(s0, s1);
#pragma unroll
            for (int o = 16; o; o >>= 1) m = fmaxf(m, __shfl_xor_sync(0xffffffffu, m, o));
            float e0 = expf(s0 - m), e1 = expf(s1 - m);
            sc[bh][l] = e0; sc[bh][l + 32] = e1;
            float ssum = wred(e0 + e1);
            if (l == 0) rz[bh] = 1.f / ssum;
        }
        __syncthreads();
        // ---- ctx: rank owns k-slice [32*rank, 32*rank+32) ----
        if (tid < 64) {
            int bh = tid >> 5, kl = tid & 31;
            const float* base = g_enc + ((b0 + bh) * 64) * 256 + 32 * rank + kl;
            float a = 0.f;
#pragma unroll 8
            for (int s = 0; s < 64; ++s) a += sc[bh][s] * __ldg(base + s * 256);
            float val = a * rz[bh];
            float* dst = ((float*)&Ctx[32 * rank + kl]) + bh;
#pragma unroll
            for (int r = 0; r < 8; ++r) stc(dst, r, val);
        }
        csync();
        // ---- gates: K=512 = [Ctx ; Hd[p]], 32 k per slice ----
        {
            const unsigned long long* hv = (q < 8)
                ? (const unsigned long long*)&Ctx[32 * q]
                : (const unsigned long long*)&Hd[p][32 * (q - 8)];
            const float4* wp = (const float4*)g_WTd + (32 * q) * 256 + colf4;
            unsigned long long a0 = 0, a1 = 0, a2 = 0, a3 = 0;
#pragma unroll
            for (int k = 0; k < 32; ++k) {
                unsigned long long hp = hv[k];
                float4 w = __ldg(wp); wp += 256;
                fma2(a0, hp, pk2(w.x, w.x));
                fma2(a1, hp, pk2(w.y, w.y));
                fma2(a2, hp, pk2(w.z, w.z));
                fma2(a3, hp, pk2(w.w, w.w));
            }
            unsigned long long* pr = (unsigned long long*)&part[q][cg * 4];
            pr[0] = a0; pr[1] = a1; pr[2] = a2; pr[3] = a3;
        }
        __syncthreads();
        if (tid < 128) {
            float sx = xa, sy = xb;
#pragma unroll
            for (int qq = 0; qq < 16; ++qq) { float2 v = part[qq][tid]; sx += v.x; sy += v.y; }
            gt[tid] = make_float2(sx, sy);
        }
        __syncthreads();
        // ---- cell (c_in = 0): h2 = sig(o)*tanh(sig(i)*tanh(g)) ----
        if (tid < 64) {
            int bh = tid >> 5, un = tid & 31;
            float gi_ = bh ? gt[un].y : gt[un].x;
            float gg_ = bh ? gt[64 + un].y : gt[64 + un].x;
            float go_ = bh ? gt[96 + un].y : gt[96 + un].x;
            float h2 = sigf(go_) * tanhf(sigf(gi_) * tanhf(gg_));
            float* dst = ((float*)&Hd[p ^ 1][32 * rank + un]) + bh;
#pragma unroll
            for (int r = 0; r < 8; ++r) stc(dst, r, h2);
            g_H2[((b0 + bh) * 100 + t) * 256 + 32 * rank + un] = h2;
        }
        csync();
    }
}

// ============================================================================
// k_out: out[r][v] = H2[r].Wout[v] + bout[v]; 128x128x16 tiles, FFMA2.
// ============================================================================
__global__ void __launch_bounds__(256) k_out(const float* __restrict__ Wout,
                                             const float* __restrict__ bout,
                                             float* __restrict__ out)
{
    __shared__ __align__(16) float As[16][132], Bs[16][132];
    const int tid = threadIdx.x;
    const int rb = blockIdx.y * 128, vb = blockIdx.x * 128;
    const int tx = tid & 15, ty = tid >> 4;
    const int r0 = tid >> 2, k0 = (tid & 3) * 4;
    const int r1 = (tid + 256) >> 2, k1 = ((tid + 256) & 3) * 4;

    unsigned long long acc[8][4];
#pragma unroll
    for (int i = 0; i < 8; ++i)
#pragma unroll
        for (int j = 0; j < 4; ++j) acc[i][j] = 0ull;

    const float* A = g_H2;
    float4 a0 = *(const float4*)(A + (rb + r0) * 256 + k0);
    float4 a1 = *(const float4*)(A + (rb + r1) * 256 + k1);
    float4 bv0 = *(const float4*)(Wout + (size_t)(vb + r0) * 256 + k0);
    float4 bv1 = *(const float4*)(Wout + (size_t)(vb + r1) * 256 + k1);

    for (int kc = 0; kc < 16; ++kc) {
        As[k0 + 0][r0] = a0.x; As[k0 + 1][r0] = a0.y; As[k0 + 2][r0] = a0.z; As[k0 + 3][r0] = a0.w;
        As[k1 + 0][r1] = a1.x; As[k1 + 1][r1] = a1.y; As[k1 + 2][r1] = a1.z; As[k1 + 3][r1] = a1.w;
        Bs[k0 + 0][r0] = bv0.x; Bs[k0 + 1][r0] = bv0.y; Bs[k0 + 2][r0] = bv0.z; Bs[k0 + 3][r0] = bv0.w;
        Bs[k1 + 0][r1] = bv1.x; Bs[k1 + 1][r1] = bv1.y; Bs[k1 + 2][r1] = bv1.z; Bs[k1 + 3][r1] = bv1.w;
        __syncthreads();
        if (kc < 15) {
            int kb = (kc + 1) * 16;
            a0 = *(const float4*)(A + (rb + r0) * 256 + kb + k0);
            a1 = *(const float4*)(A + (rb + r1) * 256 + kb + k1);
            bv0 = *(const float4*)(Wout + (size_t)(vb + r0) * 256 + kb + k0);
            bv1 = *(const float4*)(Wout + (size_t)(vb + r1) * 256 + kb + k1);
        }
#pragma unroll
        for (int k = 0; k < 16; ++k) {
            float4 aA = *(const float4*)&As[k][ty * 4];
            float4 aB = *(const float4*)&As[k][ty * 4 + 64];
            float4 bA = *(const float4*)&Bs[k][tx * 4];
            float4 bB = *(const float4*)&Bs[k][tx * 4 + 64];
            unsigned long long bp[4] = { pk2(bA.x, bA.y), pk2(bA.z, bA.w),
                                         pk2(bB.x, bB.y), pk2(bB.z, bB.w) };
            float av[8] = { aA.x, aA.y, aA.z, aA.w, aB.x, aB.y, aB.z, aB.w };
#pragma unroll
            for (int i = 0; i < 8; ++i) {
                unsigned long long ap = pk2(av[i], av[i]);
#pragma unroll
                for (int j = 0; j < 4; ++j) fma2(acc[i][j], ap, bp[j]);
            }
        }
        __syncthreads();
    }

    float bo[8];
#pragma unroll
    for (int j = 0; j < 4; ++j) {
        int cb = ((j >> 1) ? 64 : 0) + tx * 4 + (j & 1) * 2;
        bo[j * 2]     = __ldg(bout + vb + cb);
        bo[j * 2 + 1] = __ldg(bout + vb + cb + 1);
    }
#pragma unroll
    for (int i = 0; i < 8; ++i) {
        int row = rb + ((i < 4) ? (ty * 4 + i) : (64 + ty * 4 + i - 4));
        float* orow = out + (size_t)row * 32000 + vb;
#pragma unroll
        for (int j = 0; j < 4; ++j) {
            int cb = ((j >> 1) ? 64 : 0) + tx * 4 + (j & 1) * 2;
            float lo, hi; upk2(acc[i][j], lo, hi);
            *(float2*)(orow + cb) = make_float2(lo + bo[j * 2], hi + bo[j * 2 + 1]);
        }
    }
}

extern "C" void kernel_launch(void* const* d_in, const int* in_sizes, int n_in,
                              void* d_out, int out_size)
{
    (void)in_sizes; (void)n_in; (void)out_size;
    const int*   qids = (const int*)d_in[0];
    const int*   sids = (const int*)d_in[1];
    const float* encE = (const float*)d_in[2];
    const float* Wih0 = (const float*)d_in[3];
    const float* Whh0 = (const float*)d_in[4];
    const float* b0   = (const float*)d_in[5];
    const float* Wih1 = (const float*)d_in[6];
    const float* Whh1 = (const float*)d_in[7];
    const float* b1   = (const float*)d_in[8];
    const float* decE = (const float*)d_in[9];
    const float* dWih = (const float*)d_in[10];
    const float* dWhh = (const float*)d_in[11];
    const float* db   = (const float*)d_in[12];
    const float* Wout = (const float*)d_in[13];
    const float* bout = (const float*)d_in[14];
    float* out = (float*)d_out;

    k_tr<<<1280, 256>>>(Whh0, Wih1, Whh1, dWih, dWhh);
    k_pre<<<1312, 256>>>(qids, sids, encE, Wih0, b0, decE, dWih, db);
    k_enc<<<128, 512>>>(b1);
    k_dec<<<128, 512>>>();
    k_out<<<dim3(250, 25), 256>>>(Wout, bout, out);
}